// round 5
// baseline (speedup 1.0000x reference)
#include <cuda_runtime.h>
#include <cuda_bf16.h>
#include <cstdint>

// Problem constants
#define BB 64
#define NN 64
#define CC 8
#define FF 256
#define KDIM 2048   // C*F
#define ODIM 2048   // OC*OF
#define MROWS 4160  // B + B*N rows of Z
#define MPAD 4224   // padded to 33*128

// Scratch (device globals; no dynamic allocation allowed)
__device__ float g_w1s[FF];
__device__ float g_w2s[FF];
__device__ float g_s1[BB];
__device__ float g_wraw[BB * NN];
__device__ float g_t[BB * KDIM];
// adj in bf16 hi/lo split (written directly by k_adj)
__device__ __nv_bfloat16 g_adjh[(size_t)BB * CC * FF * FF];  // 67 MB
__device__ __nv_bfloat16 g_adjl[(size_t)BB * CC * FF * FF];  // 67 MB
// A-operand for znx GEMM: per b, 80 rows (64 neighbors, x, 15 pad) x KDIM
__device__ __nv_bfloat16 g_nxh[(size_t)BB * 80 * KDIM];
__device__ __nv_bfloat16 g_nxl[(size_t)BB * 80 * KDIM];
// fp32 Z (output of znx, input to quantA)
__device__ float g_Z[(size_t)MROWS * KDIM];   // 34 MB
// int8 two-digit quantization for the big GEMM
__device__ int8_t g_A1[(size_t)MPAD * KDIM];
__device__ int8_t g_A2[(size_t)MPAD * KDIM];
__device__ int8_t g_B1[(size_t)ODIM * KDIM];
__device__ int8_t g_B2[(size_t)ODIM * KDIM];
__device__ float  g_sA[MPAD];
__device__ float  g_sB[ODIM];

__device__ __forceinline__ float blockReduce256(float v) {
    __shared__ float sh[8];
    #pragma unroll
    for (int o = 16; o > 0; o >>= 1) v += __shfl_down_sync(0xffffffffu, v, o);
    int lane = threadIdx.x & 31, wid = threadIdx.x >> 5;
    if (lane == 0) sh[wid] = v;
    __syncthreads();
    if (wid == 0) {
        v = (lane < 8) ? sh[lane] : 0.f;
        #pragma unroll
        for (int o = 4; o > 0; o >>= 1) v += __shfl_down_sync(0xffffffffu, v, o);
    }
    return v;
}

__device__ __forceinline__ float blockReduceMax256(float v) {
    __shared__ float sh[8];
    #pragma unroll
    for (int o = 16; o > 0; o >>= 1) v = fmaxf(v, __shfl_down_sync(0xffffffffu, v, o));
    int lane = threadIdx.x & 31, wid = threadIdx.x >> 5;
    if (lane == 0) sh[wid] = v;
    __syncthreads();
    float r = 0.f;
    if (wid == 0) {
        r = (lane < 8) ? sh[lane] : 0.f;
        #pragma unroll
        for (int o = 4; o > 0; o >>= 1) r = fmaxf(r, __shfl_down_sync(0xffffffffu, r, o));
    }
    __shared__ float bmax;
    if (threadIdx.x == 0) bmax = r;
    __syncthreads();
    return bmax;
}

// K0: column sums of W1/W2
__global__ void k_wsum(const float* __restrict__ W1, const float* __restrict__ W2) {
    int f = threadIdx.x;
    float a = 0.f, b = 0.f;
    #pragma unroll
    for (int k = 0; k < CC; k++) { a += W1[k * FF + f]; b += W2[k * FF + f]; }
    g_w1s[f] = a; g_w2s[f] = b;
}

// K3: t[b,c,d] = sum_n nb[b,n,c,d] * (s1[b]*wraw[b,n])
__global__ void k_t(const float* __restrict__ nb) {
    int b = blockIdx.x >> 3;
    int r = ((blockIdx.x & 7) << 8) | threadIdx.x;
    __shared__ float sw[NN];
    if (threadIdx.x < NN)
        sw[threadIdx.x] = g_wraw[b * NN + threadIdx.x] * g_s1[b];
    __syncthreads();
    const float* p = nb + (size_t)b * NN * KDIM + r;
    float acc = 0.f;
    #pragma unroll 8
    for (int n = 0; n < NN; n++) acc += p[(size_t)n * KDIM] * sw[n];
    g_t[b * KDIM + r] = acc;
}

// K4: adj split -> bf16 hi/lo
__global__ void k_adj(const float* __restrict__ x) {
    int a = blockIdx.x, b = blockIdx.y;
    __shared__ float sxa[CC], sta[CC];
    int tid = threadIdx.x;
    if (tid < CC)            sxa[tid]      = x[b * KDIM + tid * FF + a];
    else if (tid < 2 * CC)   sta[tid - CC] = g_t[b * KDIM + (tid - CC) * FF + a];
    __syncthreads();
    int d = tid;
    float gg[CC];
    float den = 1e-7f;
    #pragma unroll
    for (int c = 0; c < CC; c++) {
        float xd = x[b * KDIM + c * FF + d];
        float td = g_t[b * KDIM + c * FF + d];
        float fa = sxa[c] * td + xd * sta[c];
        float s  = (fa > 0.f) ? 1.f : ((fa < 0.f) ? -1.f : 0.f);
        float g  = s * sqrtf(fmaxf(fabsf(fa), 1e-8f));
        gg[c] = g;
        den += fabsf(g);
    }
    float inv = 1.f / den;
    size_t base = ((size_t)(b * CC) * FF + a) * FF + d;
    #pragma unroll
    for (int c = 0; c < CC; c++) {
        float v = gg[c] * inv;
        __nv_bfloat16 h = __float2bfloat16(v);
        __nv_bfloat16 l = __float2bfloat16(v - __bfloat162float(h));
        g_adjh[base + (size_t)c * FF * FF] = h;
        g_adjl[base + (size_t)c * FF * FF] = l;
    }
}

// ---------- bf16 hi/lo split helpers ----------
__device__ __forceinline__ void split8(const float* vv, __nv_bfloat16* h, __nv_bfloat16* l) {
    #pragma unroll
    for (int i = 0; i < 8; i++) {
        h[i] = __float2bfloat16(vv[i]);
        l[i] = __float2bfloat16(vv[i] - __bfloat162float(h[i]));
    }
}

// Build 80-row A operand for znx AND fold in the s1 / wraw reductions.
__global__ void k_cvt_nx(const float* __restrict__ x, const float* __restrict__ nb) {
    int r = blockIdx.x, b = blockIdx.y;
    int c0 = threadIdx.x * 8;
    size_t orow = ((size_t)b * 80 + r) * KDIM + c0;
    __align__(16) __nv_bfloat16 h[8], l[8];
    if (r <= 64) {
        const float* src = (r < 64) ? nb + ((size_t)b * NN + r) * KDIM
                                    : x + (size_t)b * KDIM;
        const float4* p = (const float4*)(src + c0);
        float4 v0 = p[0], v1 = p[1];
        float vv[8] = {v0.x, v0.y, v0.z, v0.w, v1.x, v1.y, v1.z, v1.w};
        split8(vv, h, l);
        *(uint4*)(g_nxh + orow) = *(uint4*)&h[0];
        *(uint4*)(g_nxl + orow) = *(uint4*)&l[0];
        // fused attention-sum reductions
        const float* ws = (r < 64) ? g_w2s : g_w1s;
        float dot = 0.f;
        #pragma unroll
        for (int i = 0; i < 8; i++) dot += vv[i] * ws[(c0 + i) & (FF - 1)];
        dot = blockReduce256(dot);
        if (threadIdx.x == 0) {
            if (r < 64) g_wraw[b * NN + r] = dot;
            else        g_s1[b] = dot;
        }
    } else {
        #pragma unroll
        for (int i = 0; i < 8; i++) { h[i] = __float2bfloat16(0.f); l[i] = h[i]; }
        *(uint4*)(g_nxh + orow) = *(uint4*)&h[0];
        *(uint4*)(g_nxl + orow) = *(uint4*)&l[0];
    }
}

// ---------- int8 two-digit quantization ----------
// a ~= s * (127*A1 + A2) / 127^2 ; store scale/127 so out = sA*sB*(c1 + cc/127)
__device__ __forceinline__ uint32_t pack4(int a, int b, int c, int d) {
    return (uint32_t)(a & 0xFF) | ((uint32_t)(b & 0xFF) << 8) |
           ((uint32_t)(c & 0xFF) << 16) | ((uint32_t)(d & 0xFF) << 24);
}

__device__ __forceinline__ void quant_row(const float* __restrict__ src, size_t srow,
                                          int8_t* __restrict__ q1, int8_t* __restrict__ q2,
                                          float* __restrict__ scale, size_t orow, bool valid) {
    int c0 = threadIdx.x * 8;
    float vv[8];
    if (valid) {
        const float4* p = (const float4*)(src + srow * KDIM + c0);
        float4 v0 = p[0], v1 = p[1];
        vv[0]=v0.x; vv[1]=v0.y; vv[2]=v0.z; vv[3]=v0.w;
        vv[4]=v1.x; vv[5]=v1.y; vv[6]=v1.z; vv[7]=v1.w;
    } else {
        #pragma unroll
        for (int i = 0; i < 8; i++) vv[i] = 0.f;
    }
    float m = 0.f;
    #pragma unroll
    for (int i = 0; i < 8; i++) m = fmaxf(m, fabsf(vv[i]));
    m = blockReduceMax256(m);
    float inv = (m > 0.f) ? 127.f / m : 0.f;
    int i1[8], i2[8];
    #pragma unroll
    for (int i = 0; i < 8; i++) {
        float t = vv[i] * inv;
        int a1 = __float2int_rn(t);
        a1 = max(-127, min(127, a1));
        int a2 = __float2int_rn((t - (float)a1) * 127.f);
        a2 = max(-127, min(127, a2));
        i1[i] = a1; i2[i] = a2;
    }
    uint2 p1, p2;
    p1.x = pack4(i1[0], i1[1], i1[2], i1[3]);
    p1.y = pack4(i1[4], i1[5], i1[6], i1[7]);
    p2.x = pack4(i2[0], i2[1], i2[2], i2[3]);
    p2.y = pack4(i2[4], i2[5], i2[6], i2[7]);
    *(uint2*)(q1 + orow * KDIM + c0) = p1;
    *(uint2*)(q2 + orow * KDIM + c0) = p2;
    if (threadIdx.x == 0) scale[orow] = m * (1.f / 127.f);
}

__global__ void k_quantW(const float* __restrict__ Wc) {
    quant_row(Wc, blockIdx.x, g_B1, g_B2, g_sB, blockIdx.x, true);
}
__global__ void k_quantA() {
    quant_row(g_Z, blockIdx.x, g_A1, g_A2, g_sA, blockIdx.x, blockIdx.x < MROWS);
}

// ---------- warp-MMA helpers (sm_80+ PTX only) ----------
__device__ __forceinline__ uint32_t smem_u32(const void* p) {
    uint32_t a;
    asm("{ .reg .u64 t; cvta.to.shared.u64 t, %1; cvt.u32.u64 %0, t; }"
        : "=r"(a) : "l"(p));
    return a;
}
__device__ __forceinline__ void cp16(uint32_t s, const void* g) {
    asm volatile("cp.async.cg.shared.global [%0], [%1], 16;" :: "r"(s), "l"(g) : "memory");
}
__device__ __forceinline__ void ldsm4(uint32_t* r, uint32_t addr) {
    asm volatile("ldmatrix.sync.aligned.m8n8.x4.shared.b16 {%0,%1,%2,%3}, [%4];"
                 : "=r"(r[0]), "=r"(r[1]), "=r"(r[2]), "=r"(r[3]) : "r"(addr));
}
__device__ __forceinline__ void mma16816(float* c, const uint32_t* a, const uint32_t* b) {
    asm volatile(
        "mma.sync.aligned.m16n8k16.row.col.f32.bf16.bf16.f32 "
        "{%0,%1,%2,%3}, {%4,%5,%6,%7}, {%8,%9}, {%0,%1,%2,%3};"
        : "+f"(c[0]), "+f"(c[1]), "+f"(c[2]), "+f"(c[3])
        : "r"(a[0]), "r"(a[1]), "r"(a[2]), "r"(a[3]), "r"(b[0]), "r"(b[1]));
}
__device__ __forceinline__ void mma16832(int* c, const uint32_t* a, const uint32_t* b) {
    asm volatile(
        "mma.sync.aligned.m16n8k32.row.col.s32.s8.s8.s32 "
        "{%0,%1,%2,%3}, {%4,%5,%6,%7}, {%8,%9}, {%0,%1,%2,%3};"
        : "+r"(c[0]), "+r"(c[1]), "+r"(c[2]), "+r"(c[3])
        : "r"(a[0]), "r"(a[1]), "r"(a[2]), "r"(a[3]), "r"(b[0]), "r"(b[1]));
}

// ====================== K5: fused zn+zx tensor GEMM (bf16, proven) ==========
#define ZROWB 80
#define ZA_TILE (80 * ZROWB)
#define ZB_TILE (256 * ZROWB)
#define ZSTAGE (2 * (ZA_TILE + ZB_TILE))
#define ZNX_SMEM (2 * ZSTAGE)

__device__ __forceinline__ void znx_load(char* smbase, int st, int kc,
                                         int tid, int b, int c) {
    uint32_t so = smem_u32(smbase) + st * ZSTAGE;
    int kb = kc << 5;
    #pragma unroll
    for (int t = 0; t < 2; t++) {
        int idx = tid + (t << 8);
        if (idx < 320) {
            int r = idx >> 2, s = idx & 3;
            size_t g = ((size_t)b * 80 + r) * KDIM + c * FF + kb + s * 8;
            uint32_t d = so + r * ZROWB + (s << 4);
            cp16(d, g_nxh + g);
            cp16(d + ZA_TILE, g_nxl + g);
        }
    }
    #pragma unroll
    for (int t = 0; t < 4; t++) {
        int idx = tid + (t << 8);
        int a = idx >> 2, s = idx & 3;
        size_t g = (((size_t)(b * CC + c)) * FF + a) * FF + kb + s * 8;
        uint32_t d = so + 2 * ZA_TILE + a * ZROWB + (s << 4);
        cp16(d, g_adjh + g);
        cp16(d + ZB_TILE, g_adjl + g);
    }
}

__global__ __launch_bounds__(256, 1) void k_znx() {
    extern __shared__ char sm[];
    uint32_t sbase = smem_u32(sm);
    int tid = threadIdx.x;
    int lane = tid & 31, wid = tid >> 5;
    int c = blockIdx.x, b = blockIdx.y;
    int wn = wid << 5;

    float acc[5][4][4];
    #pragma unroll
    for (int i = 0; i < 5; i++)
        #pragma unroll
        for (int j = 0; j < 4; j++)
            #pragma unroll
            for (int q = 0; q < 4; q++) acc[i][j][q] = 0.f;

    int a_row = ((lane >> 3) & 1) * 8 + (lane & 7);
    int a_kof = (lane >> 4) * 8;
    int b_row = wn + ((lane >> 4) & 1) * 8 + (lane & 7);
    int b_kof = ((lane >> 3) & 1) * 8;

    znx_load(sm, 0, 0, tid, b, c);
    asm volatile("cp.async.commit_group;" ::: "memory");

    for (int kc = 0; kc < 8; kc++) {
        if (kc < 7) {
            znx_load(sm, (kc + 1) & 1, kc + 1, tid, b, c);
            asm volatile("cp.async.commit_group;" ::: "memory");
            asm volatile("cp.async.wait_group 1;" ::: "memory");
        } else {
            asm volatile("cp.async.wait_group 0;" ::: "memory");
        }
        __syncthreads();
        uint32_t sA  = sbase + (kc & 1) * ZSTAGE;
        uint32_t sAl = sA + ZA_TILE;
        uint32_t sB  = sA + 2 * ZA_TILE;
        uint32_t sBl = sB + ZB_TILE;
        #pragma unroll
        for (int kk = 0; kk < 2; kk++) {
            int kb = kk << 4;
            uint32_t ah[5][4], al[5][4], bh[2][4], bl[2][4];
            uint32_t aofs = a_row * ZROWB + (kb + a_kof) * 2;
            #pragma unroll
            for (int mt = 0; mt < 5; mt++) {
                ldsm4(ah[mt], sA  + aofs + mt * 16 * ZROWB);
                ldsm4(al[mt], sAl + aofs + mt * 16 * ZROWB);
            }
            uint32_t bofs = b_row * ZROWB + (kb + b_kof) * 2;
            #pragma unroll
            for (int np = 0; np < 2; np++) {
                ldsm4(bh[np], sB  + bofs + np * 16 * ZROWB);
                ldsm4(bl[np], sBl + bofs + np * 16 * ZROWB);
            }
            #pragma unroll
            for (int mt = 0; mt < 5; mt++)
                #pragma unroll
                for (int j = 0; j < 4; j++) {
                    const uint32_t* pbh = &bh[j >> 1][(j & 1) * 2];
                    const uint32_t* pbl = &bl[j >> 1][(j & 1) * 2];
                    mma16816(acc[mt][j], ah[mt], pbh);
                    mma16816(acc[mt][j], ah[mt], pbl);
                    mma16816(acc[mt][j], al[mt], pbh);
                }
        }
        __syncthreads();
    }

    // epilogue -> fp32 g_Z (quantA reads it)
    #pragma unroll
    for (int mt = 0; mt < 5; mt++) {
        #pragma unroll
        for (int half = 0; half < 2; half++) {
            int r = mt * 16 + (lane >> 2) + half * 8;
            int zr;
            if (r < 64)       zr = 64 + b * NN + r;
            else if (r == 64) zr = b;
            else continue;
            #pragma unroll
            for (int j = 0; j < 4; j++) {
                int col = c * FF + wn + j * 8 + (lane & 3) * 2;
                *(float2*)(g_Z + (size_t)zr * KDIM + col) =
                    make_float2(acc[mt][j][half * 2], acc[mt][j][half * 2 + 1]);
            }
        }
    }
}

// ====================== K7: big GEMM on int8 IMMA ======================
// out = Z(4224x2048) @ Wc^T(2048x2048). 2-digit base-127 int8, 3 product terms.
// Same smem geometry as the proven bf16 kernel: ROWB=80 (64B payload + 16 pad).
#define NST 3
#define ROWB 80
#define TILE_B (128 * ROWB)
#define STAGE_B (4 * TILE_B)
#define GEMM_SMEM (NST * STAGE_B)

__device__ __forceinline__ void g_load_stage(char* smembase, int st, int kc,
                                             int tid, int m0, int n0) {
    uint32_t so_base = smem_u32(smembase) + st * STAGE_B;
    #pragma unroll
    for (int t = 0; t < 2; t++) {
        int idx = tid + (t << 8);
        int row = idx >> 2, seg = idx & 3;
        size_t gA = (size_t)(m0 + row) * KDIM + (kc << 6) + (seg << 4);
        size_t gB = (size_t)(n0 + row) * KDIM + (kc << 6) + (seg << 4);
        uint32_t so = so_base + row * ROWB + (seg << 4);
        cp16(so,              g_A1 + gA);
        cp16(so + TILE_B,     g_A2 + gA);
        cp16(so + 2 * TILE_B, g_B1 + gB);
        cp16(so + 3 * TILE_B, g_B2 + gB);
    }
}

__global__ __launch_bounds__(256, 1) void k_gemm_imma(float* __restrict__ out) {
    extern __shared__ char sm[];
    uint32_t sbase = smem_u32(sm);
    int tid = threadIdx.x;
    int lane = tid & 31, wid = tid >> 5;
    int m0 = blockIdx.y << 7, n0 = blockIdx.x << 7;
    int wm = (wid >> 2) << 6;
    int wn = (wid & 3) << 5;

    int c1[4][4][4], cc[4][4][4];
    #pragma unroll
    for (int i = 0; i < 4; i++)
        #pragma unroll
        for (int j = 0; j < 4; j++)
            #pragma unroll
            for (int q = 0; q < 4; q++) { c1[i][j][q] = 0; cc[i][j][q] = 0; }

    // byte-layout of s8 k32 frags == bf16 k16 frags -> identical addressing
    int a_row = wm + ((lane >> 3) & 1) * 8 + (lane & 7);
    int a_kof = (lane >> 4) * 16;   // bytes
    int b_row = wn + ((lane >> 4) & 1) * 8 + (lane & 7);
    int b_kof = ((lane >> 3) & 1) * 16;  // bytes

    g_load_stage(sm, 0, 0, tid, m0, n0);
    asm volatile("cp.async.commit_group;" ::: "memory");
    g_load_stage(sm, 1, 1, tid, m0, n0);
    asm volatile("cp.async.commit_group;" ::: "memory");

    for (int kc = 0; kc < 32; kc++) {   // K advances 64 int8 per iter
        asm volatile("cp.async.wait_group 1;" ::: "memory");
        __syncthreads();
        if (kc + 2 < 32) g_load_stage(sm, (kc + 2) % NST, kc + 2, tid, m0, n0);
        asm volatile("cp.async.commit_group;" ::: "memory");

        uint32_t sA1 = sbase + (kc % NST) * STAGE_B;
        uint32_t sA2 = sA1 + TILE_B;
        uint32_t sB1 = sA1 + 2 * TILE_B;
        uint32_t sB2 = sA1 + 3 * TILE_B;
        #pragma unroll
        for (int kk = 0; kk < 2; kk++) {   // two k32 steps
            int kb = kk << 5;              // byte offset
            uint32_t q1[4][4], q2[4][4], w1[2][4], w2[2][4];
            uint32_t aofs = a_row * ROWB + kb + a_kof;
            #pragma unroll
            for (int mt = 0; mt < 4; mt++) {
                ldsm4(q1[mt], sA1 + aofs + mt * 16 * ROWB);
                ldsm4(q2[mt], sA2 + aofs + mt * 16 * ROWB);
            }
            uint32_t bofs = b_row * ROWB + kb + b_kof;
            #pragma unroll
            for (int np = 0; np < 2; np++) {
                ldsm4(w1[np], sB1 + bofs + np * 16 * ROWB);
                ldsm4(w2[np], sB2 + bofs + np * 16 * ROWB);
            }
            #pragma unroll
            for (int mt = 0; mt < 4; mt++)
                #pragma unroll
                for (int j = 0; j < 4; j++) {
                    const uint32_t* pb1 = &w1[j >> 1][(j & 1) * 2];
                    const uint32_t* pb2 = &w2[j >> 1][(j & 1) * 2];
                    mma16832(c1[mt][j], q1[mt], pb1);
                    mma16832(cc[mt][j], q1[mt], pb2);
                    mma16832(cc[mt][j], q2[mt], pb1);
                }
        }
        __syncthreads();
    }

    // epilogue: out = sA[m]*sB[n]*(c1 + cc/127)
    #pragma unroll
    for (int mt = 0; mt < 4; mt++) {
        int r0 = m0 + wm + mt * 16 + (lane >> 2);
        #pragma unroll
        for (int j = 0; j < 4; j++) {
            int col = n0 + wn + j * 8 + (lane & 3) * 2;
            float sb0 = g_sB[col], sb1 = g_sB[col + 1];
            #pragma unroll
            for (int half = 0; half < 2; half++) {
                int row = r0 + half * 8;
                if (row < MROWS) {
                    float sa = g_sA[row];
                    float f0 = (float)c1[mt][j][half * 2] +
                               (float)cc[mt][j][half * 2] * (1.f / 127.f);
                    float f1 = (float)c1[mt][j][half * 2 + 1] +
                               (float)cc[mt][j][half * 2 + 1] * (1.f / 127.f);
                    *(float2*)(out + (size_t)row * ODIM + col) =
                        make_float2(f0 * sa * sb0, f1 * sa * sb1);
                }
            }
        }
    }
}

extern "C" void kernel_launch(void* const* d_in, const int* in_sizes, int n_in,
                              void* d_out, int out_size) {
    const float* x  = (const float*)d_in[0];  // (64,8,256)
    const float* nb = (const float*)d_in[1];  // (64,64,8,256)
    const float* W1 = (const float*)d_in[2];  // (8,256)
    const float* W2 = (const float*)d_in[3];  // (8,256)
    const float* Wc = (const float*)d_in[4];  // (2048,8,256)
    float* out = (float*)d_out;

    static bool attr_set = false;
    if (!attr_set) {
        cudaFuncSetAttribute(k_gemm_imma, cudaFuncAttributeMaxDynamicSharedMemorySize,
                             GEMM_SMEM);
        cudaFuncSetAttribute(k_znx, cudaFuncAttributeMaxDynamicSharedMemorySize,
                             ZNX_SMEM);
        attr_set = true;
    }

    k_wsum<<<1, 256>>>(W1, W2);
    k_quantW<<<ODIM, 256>>>(Wc);
    k_cvt_nx<<<dim3(80, BB), 256>>>(x, nb);
    k_t<<<512, 256>>>(nb);
    k_adj<<<dim3(FF, BB), 256>>>(x);
    k_znx<<<dim3(CC, BB), 256, ZNX_SMEM>>>();
    k_quantA<<<MPAD, 256>>>();
    k_gemm_imma<<<dim3(16, 33), 256, GEMM_SMEM>>>(out);
}

// round 6
// speedup vs baseline: 3.1648x; 3.1648x over previous
#include <cuda_runtime.h>
#include <cuda_bf16.h>
#include <cstdint>

// Problem constants
#define BB 64
#define NN 64
#define CC 8
#define FF 256
#define KDIM 2048   // C*F
#define ODIM 2048   // OC*OF
#define MROWS 4160  // B + B*N rows of Z
#define MPAD 4224   // padded to 33*128

// Scratch (device globals; no dynamic allocation allowed)
__device__ float g_w1s[FF];
__device__ float g_w2s[FF];
__device__ float g_s1[BB];
__device__ float g_wraw[BB * NN];
__device__ float g_t[BB * KDIM];
// adj in bf16 hi/lo split (written directly by k_adj)
__device__ __nv_bfloat16 g_adjh[(size_t)BB * CC * FF * FF];  // 67 MB
__device__ __nv_bfloat16 g_adjl[(size_t)BB * CC * FF * FF];  // 67 MB
// A-operand for znx GEMM: per b, 80 rows (64 neighbors, x, 15 pad) x KDIM
__device__ __nv_bfloat16 g_nxh[(size_t)BB * 80 * KDIM];
__device__ __nv_bfloat16 g_nxl[(size_t)BB * 80 * KDIM];
// bf16 hi/lo splits for the big GEMM
__device__ __nv_bfloat16 g_Zh[(size_t)MPAD * KDIM];
__device__ __nv_bfloat16 g_Zl[(size_t)MPAD * KDIM];
__device__ __nv_bfloat16 g_Wh[(size_t)ODIM * KDIM];
__device__ __nv_bfloat16 g_Wl[(size_t)ODIM * KDIM];

__device__ __forceinline__ float blockReduce256(float v) {
    __shared__ float sh[8];
    #pragma unroll
    for (int o = 16; o > 0; o >>= 1) v += __shfl_down_sync(0xffffffffu, v, o);
    int lane = threadIdx.x & 31, wid = threadIdx.x >> 5;
    if (lane == 0) sh[wid] = v;
    __syncthreads();
    if (wid == 0) {
        v = (lane < 8) ? sh[lane] : 0.f;
        #pragma unroll
        for (int o = 4; o > 0; o >>= 1) v += __shfl_down_sync(0xffffffffu, v, o);
    }
    return v;
}

// K0: column sums of W1/W2
__global__ void k_wsum(const float* __restrict__ W1, const float* __restrict__ W2) {
    int f = threadIdx.x;
    float a = 0.f, b = 0.f;
    #pragma unroll
    for (int k = 0; k < CC; k++) { a += W1[k * FF + f]; b += W2[k * FF + f]; }
    g_w1s[f] = a; g_w2s[f] = b;
}

// K3: t[b,c,d] = sum_n nb[b,n,c,d] * (s1[b]*wraw[b,n])
__global__ void k_t(const float* __restrict__ nb) {
    int b = blockIdx.x >> 3;
    int r = ((blockIdx.x & 7) << 8) | threadIdx.x;
    __shared__ float sw[NN];
    if (threadIdx.x < NN)
        sw[threadIdx.x] = g_wraw[b * NN + threadIdx.x] * g_s1[b];
    __syncthreads();
    const float* p = nb + (size_t)b * NN * KDIM + r;
    float acc = 0.f;
    #pragma unroll 8
    for (int n = 0; n < NN; n++) acc += p[(size_t)n * KDIM] * sw[n];
    g_t[b * KDIM + r] = acc;
}

// K4: adj[b,c,a,d] = sgnroot(x_a t_d + x_d t_a) / (sum_c |sgnroot| + 1e-7)
// Writes bf16 hi/lo split directly.
__global__ void k_adj(const float* __restrict__ x) {
    int a = blockIdx.x, b = blockIdx.y;
    __shared__ float sxa[CC], sta[CC];
    int tid = threadIdx.x;
    if (tid < CC)            sxa[tid]      = x[b * KDIM + tid * FF + a];
    else if (tid < 2 * CC)   sta[tid - CC] = g_t[b * KDIM + (tid - CC) * FF + a];
    __syncthreads();
    int d = tid;
    float gg[CC];
    float den = 1e-7f;
    #pragma unroll
    for (int c = 0; c < CC; c++) {
        float xd = x[b * KDIM + c * FF + d];
        float td = g_t[b * KDIM + c * FF + d];
        float fa = sxa[c] * td + xd * sta[c];
        float s  = (fa > 0.f) ? 1.f : ((fa < 0.f) ? -1.f : 0.f);
        float g  = s * sqrtf(fmaxf(fabsf(fa), 1e-8f));
        gg[c] = g;
        den += fabsf(g);
    }
    float inv = 1.f / den;
    size_t base = ((size_t)(b * CC) * FF + a) * FF + d;
    #pragma unroll
    for (int c = 0; c < CC; c++) {
        float v = gg[c] * inv;
        __nv_bfloat16 h = __float2bfloat16(v);
        __nv_bfloat16 l = __float2bfloat16(v - __bfloat162float(h));
        g_adjh[base + (size_t)c * FF * FF] = h;
        g_adjl[base + (size_t)c * FF * FF] = l;
    }
}

// ---------- bf16 hi/lo split helpers ----------
__device__ __forceinline__ void split8(const float* vv, __nv_bfloat16* h, __nv_bfloat16* l) {
    #pragma unroll
    for (int i = 0; i < 8; i++) {
        h[i] = __float2bfloat16(vv[i]);
        l[i] = __float2bfloat16(vv[i] - __bfloat162float(h[i]));
    }
}

__global__ void k_cvt_W(const float* __restrict__ Wc) {
    size_t row = blockIdx.x;
    int c0 = threadIdx.x * 8;
    const float4* p = (const float4*)(Wc + row * KDIM + c0);
    float4 v0 = p[0], v1 = p[1];
    float vv[8] = {v0.x, v0.y, v0.z, v0.w, v1.x, v1.y, v1.z, v1.w};
    __align__(16) __nv_bfloat16 h[8], l[8];
    split8(vv, h, l);
    *(uint4*)(g_Wh + row * KDIM + c0) = *(uint4*)&h[0];
    *(uint4*)(g_Wl + row * KDIM + c0) = *(uint4*)&l[0];
}

// Build 80-row A operand for znx AND fold in the s1 / wraw reductions.
__global__ void k_cvt_nx(const float* __restrict__ x, const float* __restrict__ nb) {
    int r = blockIdx.x, b = blockIdx.y;
    int c0 = threadIdx.x * 8;
    size_t orow = ((size_t)b * 80 + r) * KDIM + c0;
    __align__(16) __nv_bfloat16 h[8], l[8];
    if (r <= 64) {
        const float* src = (r < 64) ? nb + ((size_t)b * NN + r) * KDIM
                                    : x + (size_t)b * KDIM;
        const float4* p = (const float4*)(src + c0);
        float4 v0 = p[0], v1 = p[1];
        float vv[8] = {v0.x, v0.y, v0.z, v0.w, v1.x, v1.y, v1.z, v1.w};
        split8(vv, h, l);
        *(uint4*)(g_nxh + orow) = *(uint4*)&h[0];
        *(uint4*)(g_nxl + orow) = *(uint4*)&l[0];
        // fused attention-sum reductions (replaces k_s1 and k_w)
        const float* ws = (r < 64) ? g_w2s : g_w1s;
        float dot = 0.f;
        #pragma unroll
        for (int i = 0; i < 8; i++) dot += vv[i] * ws[(c0 + i) & (FF - 1)];
        dot = blockReduce256(dot);
        if (threadIdx.x == 0) {
            if (r < 64) g_wraw[b * NN + r] = dot;
            else        g_s1[b] = dot;
        }
    } else {
        #pragma unroll
        for (int i = 0; i < 8; i++) { h[i] = __float2bfloat16(0.f); l[i] = h[i]; }
        *(uint4*)(g_nxh + orow) = *(uint4*)&h[0];
        *(uint4*)(g_nxl + orow) = *(uint4*)&l[0];
    }
}

// Zero the pad rows MROWS..MPAD of Zh/Zl (read by the big GEMM)
__global__ void k_zero_pad() {
    size_t row = MROWS + blockIdx.x;
    uint4 z = make_uint4(0, 0, 0, 0);
    *(uint4*)(g_Zh + row * KDIM + threadIdx.x * 8) = z;
    *(uint4*)(g_Zl + row * KDIM + threadIdx.x * 8) = z;
}

// ---------- warp-MMA helpers (sm_80+ PTX only) ----------
__device__ __forceinline__ uint32_t smem_u32(const void* p) {
    uint32_t a;
    asm("{ .reg .u64 t; cvta.to.shared.u64 t, %1; cvt.u32.u64 %0, t; }"
        : "=r"(a) : "l"(p));
    return a;
}
__device__ __forceinline__ void cp16(uint32_t s, const void* g) {
    asm volatile("cp.async.cg.shared.global [%0], [%1], 16;" :: "r"(s), "l"(g) : "memory");
}
__device__ __forceinline__ void ldsm4(uint32_t* r, uint32_t addr) {
    asm volatile("ldmatrix.sync.aligned.m8n8.x4.shared.b16 {%0,%1,%2,%3}, [%4];"
                 : "=r"(r[0]), "=r"(r[1]), "=r"(r[2]), "=r"(r[3]) : "r"(addr));
}
__device__ __forceinline__ void mma16816(float* c, const uint32_t* a, const uint32_t* b) {
    asm volatile(
        "mma.sync.aligned.m16n8k16.row.col.f32.bf16.bf16.f32 "
        "{%0,%1,%2,%3}, {%4,%5,%6,%7}, {%8,%9}, {%0,%1,%2,%3};"
        : "+f"(c[0]), "+f"(c[1]), "+f"(c[2]), "+f"(c[3])
        : "r"(a[0]), "r"(a[1]), "r"(a[2]), "r"(a[3]), "r"(b[0]), "r"(b[1]));
}

// ====================== K5: fused zn+zx tensor GEMM ======================
// Per (b,c): C[n=80, a=256] = NbX[80 x 256k] @ Adj[a=256 x 256k]^T, 3-term split.
// 8 warps: each covers full M=80 (5 m16 frags) x N=32. K-chunk 32, 3-stage.
#define ZNST 3
#define ZROWB 80
#define ZA_TILE (80 * ZROWB)       // 6400
#define ZB_TILE (256 * ZROWB)      // 20480
#define ZSTAGE (2 * (ZA_TILE + ZB_TILE))  // 53760
#define ZNX_SMEM (ZNST * ZSTAGE)   // 161280

__device__ __forceinline__ void znx_load(char* smbase, int st, int kc,
                                         int tid, int b, int c) {
    uint32_t so = smem_u32(smbase) + st * ZSTAGE;
    int kb = kc << 5;
    #pragma unroll
    for (int t = 0; t < 2; t++) {
        int idx = tid + (t << 8);
        if (idx < 320) {
            int r = idx >> 2, s = idx & 3;
            size_t g = ((size_t)b * 80 + r) * KDIM + c * FF + kb + s * 8;
            uint32_t d = so + r * ZROWB + (s << 4);
            cp16(d, g_nxh + g);
            cp16(d + ZA_TILE, g_nxl + g);
        }
    }
    #pragma unroll
    for (int t = 0; t < 4; t++) {
        int idx = tid + (t << 8);
        int a = idx >> 2, s = idx & 3;
        size_t g = (((size_t)(b * CC + c)) * FF + a) * FF + kb + s * 8;
        uint32_t d = so + 2 * ZA_TILE + a * ZROWB + (s << 4);
        cp16(d, g_adjh + g);
        cp16(d + ZB_TILE, g_adjl + g);
    }
}

__global__ __launch_bounds__(256, 1) void k_znx() {
    extern __shared__ char sm[];
    uint32_t sbase = smem_u32(sm);
    int tid = threadIdx.x;
    int lane = tid & 31, wid = tid >> 5;
    int c = blockIdx.x, b = blockIdx.y;
    int wn = wid << 5;

    float acc[5][4][4];
    #pragma unroll
    for (int i = 0; i < 5; i++)
        #pragma unroll
        for (int j = 0; j < 4; j++)
            #pragma unroll
            for (int q = 0; q < 4; q++) acc[i][j][q] = 0.f;

    int a_row = ((lane >> 3) & 1) * 8 + (lane & 7);
    int a_kof = (lane >> 4) * 8;
    int b_row = wn + ((lane >> 4) & 1) * 8 + (lane & 7);
    int b_kof = ((lane >> 3) & 1) * 8;

    znx_load(sm, 0, 0, tid, b, c);
    asm volatile("cp.async.commit_group;" ::: "memory");
    znx_load(sm, 1, 1, tid, b, c);
    asm volatile("cp.async.commit_group;" ::: "memory");

    for (int kc = 0; kc < 8; kc++) {
        asm volatile("cp.async.wait_group 1;" ::: "memory");
        __syncthreads();
        if (kc + 2 < 8) znx_load(sm, (kc + 2) % ZNST, kc + 2, tid, b, c);
        asm volatile("cp.async.commit_group;" ::: "memory");

        uint32_t sA  = sbase + (kc % ZNST) * ZSTAGE;
        uint32_t sAl = sA + ZA_TILE;
        uint32_t sB  = sA + 2 * ZA_TILE;
        uint32_t sBl = sB + ZB_TILE;
        #pragma unroll
        for (int kk = 0; kk < 2; kk++) {
            int kb = kk << 4;
            uint32_t ah[5][4], al[5][4], bh[2][4], bl[2][4];
            uint32_t aofs = a_row * ZROWB + (kb + a_kof) * 2;
            #pragma unroll
            for (int mt = 0; mt < 5; mt++) {
                ldsm4(ah[mt], sA  + aofs + mt * 16 * ZROWB);
                ldsm4(al[mt], sAl + aofs + mt * 16 * ZROWB);
            }
            uint32_t bofs = b_row * ZROWB + (kb + b_kof) * 2;
            #pragma unroll
            for (int np = 0; np < 2; np++) {
                ldsm4(bh[np], sB  + bofs + np * 16 * ZROWB);
                ldsm4(bl[np], sBl + bofs + np * 16 * ZROWB);
            }
            #pragma unroll
            for (int mt = 0; mt < 5; mt++)
                #pragma unroll
                for (int j = 0; j < 4; j++) {
                    const uint32_t* pbh = &bh[j >> 1][(j & 1) * 2];
                    const uint32_t* pbl = &bl[j >> 1][(j & 1) * 2];
                    mma16816(acc[mt][j], ah[mt], pbh);
                    mma16816(acc[mt][j], ah[mt], pbl);
                    mma16816(acc[mt][j], al[mt], pbh);
                }
        }
        __syncthreads();
    }

    // epilogue: rows = n (x at n==64), cols = a; write bf16 split into Zh/Zl
    #pragma unroll
    for (int mt = 0; mt < 5; mt++) {
        #pragma unroll
        for (int half = 0; half < 2; half++) {
            int r = mt * 16 + (lane >> 2) + half * 8;
            int zr;
            if (r < 64)       zr = 64 + b * NN + r;
            else if (r == 64) zr = b;
            else continue;
            #pragma unroll
            for (int j = 0; j < 4; j++) {
                int col = c * FF + wn + j * 8 + (lane & 3) * 2;
                float v0 = acc[mt][j][half * 2], v1 = acc[mt][j][half * 2 + 1];
                __nv_bfloat16 h0 = __float2bfloat16(v0);
                __nv_bfloat16 h1 = __float2bfloat16(v1);
                __nv_bfloat16 l0 = __float2bfloat16(v0 - __bfloat162float(h0));
                __nv_bfloat16 l1 = __float2bfloat16(v1 - __bfloat162float(h1));
                *(__nv_bfloat162*)(g_Zh + (size_t)zr * KDIM + col) =
                    __nv_bfloat162{h0, h1};
                *(__nv_bfloat162*)(g_Zl + (size_t)zr * KDIM + col) =
                    __nv_bfloat162{l0, l1};
            }
        }
    }
}

// ====================== K7: big GEMM (bf16 3-term, proven) ======================
#define NST 3
#define ROWB 80
#define TILE_B (128 * ROWB)
#define STAGE_B (4 * TILE_B)
#define GEMM_SMEM (NST * STAGE_B)

__device__ __forceinline__ void g_load_stage(char* smembase, int st, int kc,
                                             int tid, int m0, int n0) {
    uint32_t so_base = smem_u32(smembase) + st * STAGE_B;
    #pragma unroll
    for (int t = 0; t < 2; t++) {
        int idx = tid + (t << 8);
        int row = idx >> 2, seg = idx & 3;
        size_t gA = (size_t)(m0 + row) * KDIM + (kc << 5) + (seg << 3);
        size_t gB = (size_t)(n0 + row) * KDIM + (kc << 5) + (seg << 3);
        uint32_t so = so_base + row * ROWB + (seg << 4);
        cp16(so,              g_Zh + gA);
        cp16(so + TILE_B,     g_Zl + gA);
        cp16(so + 2 * TILE_B, g_Wh + gB);
        cp16(so + 3 * TILE_B, g_Wl + gB);
    }
}

__global__ __launch_bounds__(256, 1) void k_gemm_mma(float* __restrict__ out) {
    extern __shared__ char sm[];
    uint32_t sbase = smem_u32(sm);
    int tid = threadIdx.x;
    int lane = tid & 31, wid = tid >> 5;
    int m0 = blockIdx.y << 7, n0 = blockIdx.x << 7;
    int wm = (wid >> 2) << 6;
    int wn = (wid & 3) << 5;

    float c[4][4][4];
    #pragma unroll
    for (int i = 0; i < 4; i++)
        #pragma unroll
        for (int j = 0; j < 4; j++)
            #pragma unroll
            for (int q = 0; q < 4; q++) c[i][j][q] = 0.f;

    int a_row = wm + ((lane >> 3) & 1) * 8 + (lane & 7);
    int a_kof = (lane >> 4) * 8;
    int b_row = wn + ((lane >> 4) & 1) * 8 + (lane & 7);
    int b_kof = ((lane >> 3) & 1) * 8;

    g_load_stage(sm, 0, 0, tid, m0, n0);
    asm volatile("cp.async.commit_group;" ::: "memory");
    g_load_stage(sm, 1, 1, tid, m0, n0);
    asm volatile("cp.async.commit_group;" ::: "memory");

    for (int kc = 0; kc < 64; kc++) {
        asm volatile("cp.async.wait_group 1;" ::: "memory");
        __syncthreads();
        if (kc + 2 < 64) g_load_stage(sm, (kc + 2) % NST, kc + 2, tid, m0, n0);
        asm volatile("cp.async.commit_group;" ::: "memory");

        uint32_t sA  = sbase + (kc % NST) * STAGE_B;
        uint32_t sAl = sA + TILE_B;
        uint32_t sB  = sA + 2 * TILE_B;
        uint32_t sBl = sA + 3 * TILE_B;
        #pragma unroll
        for (int kk = 0; kk < 2; kk++) {
            int kb = kk << 4;
            uint32_t ah[4][4], al[4][4], bh[2][4], bl[2][4];
            uint32_t aofs = a_row * ROWB + (kb + a_kof) * 2;
            #pragma unroll
            for (int mt = 0; mt < 4; mt++) {
                ldsm4(ah[mt], sA  + aofs + mt * 16 * ROWB);
                ldsm4(al[mt], sAl + aofs + mt * 16 * ROWB);
            }
            uint32_t bofs = b_row * ROWB + (kb + b_kof) * 2;
            #pragma unroll
            for (int np = 0; np < 2; np++) {
                ldsm4(bh[np], sB  + bofs + np * 16 * ROWB);
                ldsm4(bl[np], sBl + bofs + np * 16 * ROWB);
            }
            #pragma unroll
            for (int mt = 0; mt < 4; mt++)
                #pragma unroll
                for (int j = 0; j < 4; j++) {
                    const uint32_t* pbh = &bh[j >> 1][(j & 1) * 2];
                    const uint32_t* pbl = &bl[j >> 1][(j & 1) * 2];
                    mma16816(c[mt][j], ah[mt], pbh);
                    mma16816(c[mt][j], ah[mt], pbl);
                    mma16816(c[mt][j], al[mt], pbh);
                }
        }
        __syncthreads();
    }

    #pragma unroll
    for (int mt = 0; mt < 4; mt++) {
        int r0 = m0 + wm + mt * 16 + (lane >> 2);
        #pragma unroll
        for (int j = 0; j < 4; j++) {
            int col = n0 + wn + j * 8 + (lane & 3) * 2;
            if (r0 < MROWS)
                *(float2*)(out + (size_t)r0 * ODIM + col) =
                    make_float2(c[mt][j][0], c[mt][j][1]);
            if (r0 + 8 < MROWS)
                *(float2*)(out + (size_t)(r0 + 8) * ODIM + col) =
                    make_float2(c[mt][j][2], c[mt][j][3]);
        }
    }
}

extern "C" void kernel_launch(void* const* d_in, const int* in_sizes, int n_in,
                              void* d_out, int out_size) {
    const float* x  = (const float*)d_in[0];  // (64,8,256)
    const float* nb = (const float*)d_in[1];  // (64,64,8,256)
    const float* W1 = (const float*)d_in[2];  // (8,256)
    const float* W2 = (const float*)d_in[3];  // (8,256)
    const float* Wc = (const float*)d_in[4];  // (2048,8,256)
    float* out = (float*)d_out;

    static bool attr_set = false;
    if (!attr_set) {
        cudaFuncSetAttribute(k_gemm_mma, cudaFuncAttributeMaxDynamicSharedMemorySize,
                             GEMM_SMEM);
        cudaFuncSetAttribute(k_znx, cudaFuncAttributeMaxDynamicSharedMemorySize,
                             ZNX_SMEM);
        attr_set = true;
    }

    k_wsum<<<1, 256>>>(W1, W2);
    k_cvt_W<<<ODIM, 256>>>(Wc);
    k_cvt_nx<<<dim3(80, BB), 256>>>(x, nb);
    k_t<<<512, 256>>>(nb);
    k_adj<<<dim3(FF, BB), 256>>>(x);
    k_zero_pad<<<MPAD - MROWS, 256>>>();
    k_znx<<<dim3(CC, BB), 256, ZNX_SMEM>>>();
    k_gemm_mma<<<dim3(16, 33), 256, GEMM_SMEM>>>(out);
}

// round 7
// speedup vs baseline: 4.0957x; 1.2941x over previous
#include <cuda_runtime.h>
#include <cuda_bf16.h>
#include <cuda_fp16.h>
#include <cstdint>

// Problem constants
#define BB 64
#define NN 64
#define CC 8
#define FF 256
#define KDIM 2048   // C*F
#define ODIM 2048   // OC*OF
#define MROWS 4160  // B + B*N rows of Z
#define MPAD 4224   // padded to 33*128

// Scratch (device globals; no dynamic allocation allowed)
__device__ float g_w1s[FF];
__device__ float g_w2s[FF];
__device__ float g_s1[BB];
__device__ float g_wraw[BB * NN];
__device__ float g_t[BB * KDIM];
// adj in bf16 hi/lo split (written directly by k_adj)
__device__ __nv_bfloat16 g_adjh[(size_t)BB * CC * FF * FF];  // 67 MB
__device__ __nv_bfloat16 g_adjl[(size_t)BB * CC * FF * FF];  // 67 MB
// A-operand for znx GEMM: per b, 80 rows (64 neighbors, x, 15 pad) x KDIM
__device__ __nv_bfloat16 g_nxh[(size_t)BB * 80 * KDIM];
__device__ __nv_bfloat16 g_nxl[(size_t)BB * 80 * KDIM];
// fp16 splits for the big GEMM: Z two-digit, W single-digit
__device__ __half g_Zh[(size_t)MPAD * KDIM];
__device__ __half g_Zl[(size_t)MPAD * KDIM];
__device__ __half g_Wh[(size_t)ODIM * KDIM];

__device__ __forceinline__ float blockReduce256(float v) {
    __shared__ float sh[8];
    #pragma unroll
    for (int o = 16; o > 0; o >>= 1) v += __shfl_down_sync(0xffffffffu, v, o);
    int lane = threadIdx.x & 31, wid = threadIdx.x >> 5;
    if (lane == 0) sh[wid] = v;
    __syncthreads();
    if (wid == 0) {
        v = (lane < 8) ? sh[lane] : 0.f;
        #pragma unroll
        for (int o = 4; o > 0; o >>= 1) v += __shfl_down_sync(0xffffffffu, v, o);
    }
    return v;
}

// K0: column sums of W1/W2
__global__ void k_wsum(const float* __restrict__ W1, const float* __restrict__ W2) {
    int f = threadIdx.x;
    float a = 0.f, b = 0.f;
    #pragma unroll
    for (int k = 0; k < CC; k++) { a += W1[k * FF + f]; b += W2[k * FF + f]; }
    g_w1s[f] = a; g_w2s[f] = b;
}

// K3: t[b,c,d] = sum_n nb[b,n,c,d] * (s1[b]*wraw[b,n])
__global__ void k_t(const float* __restrict__ nb) {
    int b = blockIdx.x >> 3;
    int r = ((blockIdx.x & 7) << 8) | threadIdx.x;
    __shared__ float sw[NN];
    if (threadIdx.x < NN)
        sw[threadIdx.x] = g_wraw[b * NN + threadIdx.x] * g_s1[b];
    __syncthreads();
    const float* p = nb + (size_t)b * NN * KDIM + r;
    float acc = 0.f;
    #pragma unroll 8
    for (int n = 0; n < NN; n++) acc += p[(size_t)n * KDIM] * sw[n];
    g_t[b * KDIM + r] = acc;
}

// K4: adj[b,c,a,d] = sgnroot(x_a t_d + x_d t_a) / (sum_c |sgnroot| + 1e-7)
// Writes bf16 hi/lo split directly.
__global__ void k_adj(const float* __restrict__ x) {
    int a = blockIdx.x, b = blockIdx.y;
    __shared__ float sxa[CC], sta[CC];
    int tid = threadIdx.x;
    if (tid < CC)            sxa[tid]      = x[b * KDIM + tid * FF + a];
    else if (tid < 2 * CC)   sta[tid - CC] = g_t[b * KDIM + (tid - CC) * FF + a];
    __syncthreads();
    int d = tid;
    float gg[CC];
    float den = 1e-7f;
    #pragma unroll
    for (int c = 0; c < CC; c++) {
        float xd = x[b * KDIM + c * FF + d];
        float td = g_t[b * KDIM + c * FF + d];
        float fa = sxa[c] * td + xd * sta[c];
        float s  = (fa > 0.f) ? 1.f : ((fa < 0.f) ? -1.f : 0.f);
        float g  = s * sqrtf(fmaxf(fabsf(fa), 1e-8f));
        gg[c] = g;
        den += fabsf(g);
    }
    float inv = 1.f / den;
    size_t base = ((size_t)(b * CC) * FF + a) * FF + d;
    #pragma unroll
    for (int c = 0; c < CC; c++) {
        float v = gg[c] * inv;
        __nv_bfloat16 h = __float2bfloat16(v);
        __nv_bfloat16 l = __float2bfloat16(v - __bfloat162float(h));
        g_adjh[base + (size_t)c * FF * FF] = h;
        g_adjl[base + (size_t)c * FF * FF] = l;
    }
}

// ---------- split helpers ----------
__device__ __forceinline__ void split8(const float* vv, __nv_bfloat16* h, __nv_bfloat16* l) {
    #pragma unroll
    for (int i = 0; i < 8; i++) {
        h[i] = __float2bfloat16(vv[i]);
        l[i] = __float2bfloat16(vv[i] - __bfloat162float(h[i]));
    }
}

// W -> single fp16
__global__ void k_cvt_W(const float* __restrict__ Wc) {
    size_t row = blockIdx.x;
    int c0 = threadIdx.x * 8;
    const float4* p = (const float4*)(Wc + row * KDIM + c0);
    float4 v0 = p[0], v1 = p[1];
    float vv[8] = {v0.x, v0.y, v0.z, v0.w, v1.x, v1.y, v1.z, v1.w};
    __align__(16) __half h[8];
    #pragma unroll
    for (int i = 0; i < 8; i++) h[i] = __float2half_rn(vv[i]);
    *(uint4*)(g_Wh + row * KDIM + c0) = *(uint4*)&h[0];
}

// Build 80-row A operand for znx AND fold in the s1 / wraw reductions.
__global__ void k_cvt_nx(const float* __restrict__ x, const float* __restrict__ nb) {
    int r = blockIdx.x, b = blockIdx.y;
    int c0 = threadIdx.x * 8;
    size_t orow = ((size_t)b * 80 + r) * KDIM + c0;
    __align__(16) __nv_bfloat16 h[8], l[8];
    if (r <= 64) {
        const float* src = (r < 64) ? nb + ((size_t)b * NN + r) * KDIM
                                    : x + (size_t)b * KDIM;
        const float4* p = (const float4*)(src + c0);
        float4 v0 = p[0], v1 = p[1];
        float vv[8] = {v0.x, v0.y, v0.z, v0.w, v1.x, v1.y, v1.z, v1.w};
        split8(vv, h, l);
        *(uint4*)(g_nxh + orow) = *(uint4*)&h[0];
        *(uint4*)(g_nxl + orow) = *(uint4*)&l[0];
        // fused attention-sum reductions (replaces k_s1 and k_w)
        const float* ws = (r < 64) ? g_w2s : g_w1s;
        float dot = 0.f;
        #pragma unroll
        for (int i = 0; i < 8; i++) dot += vv[i] * ws[(c0 + i) & (FF - 1)];
        dot = blockReduce256(dot);
        if (threadIdx.x == 0) {
            if (r < 64) g_wraw[b * NN + r] = dot;
            else        g_s1[b] = dot;
        }
    } else {
        #pragma unroll
        for (int i = 0; i < 8; i++) { h[i] = __float2bfloat16(0.f); l[i] = h[i]; }
        *(uint4*)(g_nxh + orow) = *(uint4*)&h[0];
        *(uint4*)(g_nxl + orow) = *(uint4*)&l[0];
    }
}

// Zero the pad rows MROWS..MPAD of Zh/Zl (read by the big GEMM)
__global__ void k_zero_pad() {
    size_t row = MROWS + blockIdx.x;
    uint4 z = make_uint4(0, 0, 0, 0);
    *(uint4*)(g_Zh + row * KDIM + threadIdx.x * 8) = z;
    *(uint4*)(g_Zl + row * KDIM + threadIdx.x * 8) = z;
}

// ---------- warp-MMA helpers (sm_80+ PTX only) ----------
__device__ __forceinline__ uint32_t smem_u32(const void* p) {
    uint32_t a;
    asm("{ .reg .u64 t; cvta.to.shared.u64 t, %1; cvt.u32.u64 %0, t; }"
        : "=r"(a) : "l"(p));
    return a;
}
__device__ __forceinline__ void cp16(uint32_t s, const void* g) {
    asm volatile("cp.async.cg.shared.global [%0], [%1], 16;" :: "r"(s), "l"(g) : "memory");
}
__device__ __forceinline__ void ldsm4(uint32_t* r, uint32_t addr) {
    asm volatile("ldmatrix.sync.aligned.m8n8.x4.shared.b16 {%0,%1,%2,%3}, [%4];"
                 : "=r"(r[0]), "=r"(r[1]), "=r"(r[2]), "=r"(r[3]) : "r"(addr));
}
__device__ __forceinline__ void mma16816(float* c, const uint32_t* a, const uint32_t* b) {
    asm volatile(
        "mma.sync.aligned.m16n8k16.row.col.f32.bf16.bf16.f32 "
        "{%0,%1,%2,%3}, {%4,%5,%6,%7}, {%8,%9}, {%0,%1,%2,%3};"
        : "+f"(c[0]), "+f"(c[1]), "+f"(c[2]), "+f"(c[3])
        : "r"(a[0]), "r"(a[1]), "r"(a[2]), "r"(a[3]), "r"(b[0]), "r"(b[1]));
}
__device__ __forceinline__ void mma16816h(float* c, const uint32_t* a, const uint32_t* b) {
    asm volatile(
        "mma.sync.aligned.m16n8k16.row.col.f32.f16.f16.f32 "
        "{%0,%1,%2,%3}, {%4,%5,%6,%7}, {%8,%9}, {%0,%1,%2,%3};"
        : "+f"(c[0]), "+f"(c[1]), "+f"(c[2]), "+f"(c[3])
        : "r"(a[0]), "r"(a[1]), "r"(a[2]), "r"(a[3]), "r"(b[0]), "r"(b[1]));
}

// ====================== K5: fused zn+zx tensor GEMM (bf16 3-term) ==========
#define ZNST 3
#define ZROWB 80
#define ZA_TILE (80 * ZROWB)
#define ZB_TILE (256 * ZROWB)
#define ZSTAGE (2 * (ZA_TILE + ZB_TILE))
#define ZNX_SMEM (ZNST * ZSTAGE)

__device__ __forceinline__ void znx_load(char* smbase, int st, int kc,
                                         int tid, int b, int c) {
    uint32_t so = smem_u32(smbase) + st * ZSTAGE;
    int kb = kc << 5;
    #pragma unroll
    for (int t = 0; t < 2; t++) {
        int idx = tid + (t << 8);
        if (idx < 320) {
            int r = idx >> 2, s = idx & 3;
            size_t g = ((size_t)b * 80 + r) * KDIM + c * FF + kb + s * 8;
            uint32_t d = so + r * ZROWB + (s << 4);
            cp16(d, g_nxh + g);
            cp16(d + ZA_TILE, g_nxl + g);
        }
    }
    #pragma unroll
    for (int t = 0; t < 4; t++) {
        int idx = tid + (t << 8);
        int a = idx >> 2, s = idx & 3;
        size_t g = (((size_t)(b * CC + c)) * FF + a) * FF + kb + s * 8;
        uint32_t d = so + 2 * ZA_TILE + a * ZROWB + (s << 4);
        cp16(d, g_adjh + g);
        cp16(d + ZB_TILE, g_adjl + g);
    }
}

__global__ __launch_bounds__(256, 1) void k_znx() {
    extern __shared__ char sm[];
    uint32_t sbase = smem_u32(sm);
    int tid = threadIdx.x;
    int lane = tid & 31, wid = tid >> 5;
    int c = blockIdx.x, b = blockIdx.y;
    int wn = wid << 5;

    float acc[5][4][4];
    #pragma unroll
    for (int i = 0; i < 5; i++)
        #pragma unroll
        for (int j = 0; j < 4; j++)
            #pragma unroll
            for (int q = 0; q < 4; q++) acc[i][j][q] = 0.f;

    int a_row = ((lane >> 3) & 1) * 8 + (lane & 7);
    int a_kof = (lane >> 4) * 8;
    int b_row = wn + ((lane >> 4) & 1) * 8 + (lane & 7);
    int b_kof = ((lane >> 3) & 1) * 8;

    znx_load(sm, 0, 0, tid, b, c);
    asm volatile("cp.async.commit_group;" ::: "memory");
    znx_load(sm, 1, 1, tid, b, c);
    asm volatile("cp.async.commit_group;" ::: "memory");

    for (int kc = 0; kc < 8; kc++) {
        asm volatile("cp.async.wait_group 1;" ::: "memory");
        __syncthreads();
        if (kc + 2 < 8) znx_load(sm, (kc + 2) % ZNST, kc + 2, tid, b, c);
        asm volatile("cp.async.commit_group;" ::: "memory");

        uint32_t sA  = sbase + (kc % ZNST) * ZSTAGE;
        uint32_t sAl = sA + ZA_TILE;
        uint32_t sB  = sA + 2 * ZA_TILE;
        uint32_t sBl = sB + ZB_TILE;
        #pragma unroll
        for (int kk = 0; kk < 2; kk++) {
            int kb = kk << 4;
            uint32_t ah[5][4], al[5][4], bh[2][4], bl[2][4];
            uint32_t aofs = a_row * ZROWB + (kb + a_kof) * 2;
            #pragma unroll
            for (int mt = 0; mt < 5; mt++) {
                ldsm4(ah[mt], sA  + aofs + mt * 16 * ZROWB);
                ldsm4(al[mt], sAl + aofs + mt * 16 * ZROWB);
            }
            uint32_t bofs = b_row * ZROWB + (kb + b_kof) * 2;
            #pragma unroll
            for (int np = 0; np < 2; np++) {
                ldsm4(bh[np], sB  + bofs + np * 16 * ZROWB);
                ldsm4(bl[np], sBl + bofs + np * 16 * ZROWB);
            }
            #pragma unroll
            for (int mt = 0; mt < 5; mt++)
                #pragma unroll
                for (int j = 0; j < 4; j++) {
                    const uint32_t* pbh = &bh[j >> 1][(j & 1) * 2];
                    const uint32_t* pbl = &bl[j >> 1][(j & 1) * 2];
                    mma16816(acc[mt][j], ah[mt], pbh);
                    mma16816(acc[mt][j], ah[mt], pbl);
                    mma16816(acc[mt][j], al[mt], pbh);
                }
        }
        __syncthreads();
    }

    // epilogue: rows = n (x at n==64), cols = a; write fp16 2-digit split Zh/Zl
    #pragma unroll
    for (int mt = 0; mt < 5; mt++) {
        #pragma unroll
        for (int half = 0; half < 2; half++) {
            int r = mt * 16 + (lane >> 2) + half * 8;
            int zr;
            if (r < 64)       zr = 64 + b * NN + r;
            else if (r == 64) zr = b;
            else continue;
            #pragma unroll
            for (int j = 0; j < 4; j++) {
                int col = c * FF + wn + j * 8 + (lane & 3) * 2;
                float v0 = acc[mt][j][half * 2], v1 = acc[mt][j][half * 2 + 1];
                __half h0 = __float2half_rn(v0);
                __half h1 = __float2half_rn(v1);
                __half l0 = __float2half_rn(v0 - __half2float(h0));
                __half l1 = __float2half_rn(v1 - __half2float(h1));
                *(__half2*)(g_Zh + (size_t)zr * KDIM + col) = __halves2half2(h0, h1);
                *(__half2*)(g_Zl + (size_t)zr * KDIM + col) = __halves2half2(l0, l1);
            }
        }
    }
}

// ====================== K7: big GEMM, fp16 2-MMA split ======================
// out = Z(4224x2048) @ Wc^T(2048x2048): C = Zh*Wh + Zl*Wh (W single fp16).
#define NST 4
#define ROWB 80
#define TILE_B (128 * ROWB)
#define STAGE_B (3 * TILE_B)          // Zh, Zl, Wh
#define GEMM_SMEM (NST * STAGE_B)     // 122880

__device__ __forceinline__ void g_load_stage(char* smembase, int st, int kc,
                                             int tid, int m0, int n0) {
    uint32_t so_base = smem_u32(smembase) + st * STAGE_B;
    #pragma unroll
    for (int t = 0; t < 2; t++) {
        int idx = tid + (t << 8);
        int row = idx >> 2, seg = idx & 3;
        size_t gA = (size_t)(m0 + row) * KDIM + (kc << 5) + (seg << 3);
        size_t gB = (size_t)(n0 + row) * KDIM + (kc << 5) + (seg << 3);
        uint32_t so = so_base + row * ROWB + (seg << 4);
        cp16(so,              g_Zh + gA);
        cp16(so + TILE_B,     g_Zl + gA);
        cp16(so + 2 * TILE_B, g_Wh + gB);
    }
}

__global__ __launch_bounds__(256, 1) void k_gemm_mma(float* __restrict__ out) {
    extern __shared__ char sm[];
    uint32_t sbase = smem_u32(sm);
    int tid = threadIdx.x;
    int lane = tid & 31, wid = tid >> 5;
    int m0 = blockIdx.y << 7, n0 = blockIdx.x << 7;
    int wm = (wid >> 2) << 6;
    int wn = (wid & 3) << 5;

    float c[4][4][4];
    #pragma unroll
    for (int i = 0; i < 4; i++)
        #pragma unroll
        for (int j = 0; j < 4; j++)
            #pragma unroll
            for (int q = 0; q < 4; q++) c[i][j][q] = 0.f;

    int a_row = wm + ((lane >> 3) & 1) * 8 + (lane & 7);
    int a_kof = (lane >> 4) * 8;
    int b_row = wn + ((lane >> 4) & 1) * 8 + (lane & 7);
    int b_kof = ((lane >> 3) & 1) * 8;

    g_load_stage(sm, 0, 0, tid, m0, n0);
    asm volatile("cp.async.commit_group;" ::: "memory");
    g_load_stage(sm, 1, 1, tid, m0, n0);
    asm volatile("cp.async.commit_group;" ::: "memory");
    g_load_stage(sm, 2, 2, tid, m0, n0);
    asm volatile("cp.async.commit_group;" ::: "memory");

    for (int kc = 0; kc < 64; kc++) {
        asm volatile("cp.async.wait_group 2;" ::: "memory");
        __syncthreads();
        if (kc + 3 < 64) g_load_stage(sm, (kc + 3) % NST, kc + 3, tid, m0, n0);
        asm volatile("cp.async.commit_group;" ::: "memory");

        uint32_t sA  = sbase + (kc % NST) * STAGE_B;
        uint32_t sAl = sA + TILE_B;
        uint32_t sB  = sA + 2 * TILE_B;
        #pragma unroll
        for (int kk = 0; kk < 2; kk++) {
            int kb = kk << 4;
            uint32_t ah[4][4], al[4][4], bh[2][4];
            uint32_t aofs = a_row * ROWB + (kb + a_kof) * 2;
            #pragma unroll
            for (int mt = 0; mt < 4; mt++) {
                ldsm4(ah[mt], sA  + aofs + mt * 16 * ROWB);
                ldsm4(al[mt], sAl + aofs + mt * 16 * ROWB);
            }
            uint32_t bofs = b_row * ROWB + (kb + b_kof) * 2;
            #pragma unroll
            for (int np = 0; np < 2; np++)
                ldsm4(bh[np], sB + bofs + np * 16 * ROWB);
            #pragma unroll
            for (int mt = 0; mt < 4; mt++)
                #pragma unroll
                for (int j = 0; j < 4; j++) {
                    const uint32_t* pbh = &bh[j >> 1][(j & 1) * 2];
                    mma16816h(c[mt][j], ah[mt], pbh);
                    mma16816h(c[mt][j], al[mt], pbh);
                }
        }
        __syncthreads();
    }

    #pragma unroll
    for (int mt = 0; mt < 4; mt++) {
        int r0 = m0 + wm + mt * 16 + (lane >> 2);
        #pragma unroll
        for (int j = 0; j < 4; j++) {
            int col = n0 + wn + j * 8 + (lane & 3) * 2;
            if (r0 < MROWS)
                *(float2*)(out + (size_t)r0 * ODIM + col) =
                    make_float2(c[mt][j][0], c[mt][j][1]);
            if (r0 + 8 < MROWS)
                *(float2*)(out + (size_t)(r0 + 8) * ODIM + col) =
                    make_float2(c[mt][j][2], c[mt][j][3]);
        }
    }
}

extern "C" void kernel_launch(void* const* d_in, const int* in_sizes, int n_in,
                              void* d_out, int out_size) {
    const float* x  = (const float*)d_in[0];  // (64,8,256)
    const float* nb = (const float*)d_in[1];  // (64,64,8,256)
    const float* W1 = (const float*)d_in[2];  // (8,256)
    const float* W2 = (const float*)d_in[3];  // (8,256)
    const float* Wc = (const float*)d_in[4];  // (2048,8,256)
    float* out = (float*)d_out;

    static bool attr_set = false;
    if (!attr_set) {
        cudaFuncSetAttribute(k_gemm_mma, cudaFuncAttributeMaxDynamicSharedMemorySize,
                             GEMM_SMEM);
        cudaFuncSetAttribute(k_znx, cudaFuncAttributeMaxDynamicSharedMemorySize,
                             ZNX_SMEM);
        attr_set = true;
    }

    k_wsum<<<1, 256>>>(W1, W2);
    k_cvt_W<<<ODIM, 256>>>(Wc);
    k_cvt_nx<<<dim3(80, BB), 256>>>(x, nb);
    k_t<<<512, 256>>>(nb);
    k_adj<<<dim3(FF, BB), 256>>>(x);
    k_zero_pad<<<MPAD - MROWS, 256>>>();
    k_znx<<<dim3(CC, BB), 256, ZNX_SMEM>>>();
    k_gemm_mma<<<dim3(16, 33), 256, GEMM_SMEM>>>(out);
}

// round 8
// speedup vs baseline: 5.5675x; 1.3594x over previous
#include <cuda_runtime.h>
#include <cuda_bf16.h>
#include <cuda_fp16.h>
#include <cstdint>

// Problem constants
#define BB 64
#define NN 64
#define CC 8
#define FF 256
#define KDIM 2048   // C*F
#define ODIM 2048   // OC*OF
#define MROWS 4160  // B + B*N rows of Z
#define MPAD 4224   // padded to 33*128

// Scratch (device globals; no dynamic allocation allowed)
__device__ float g_w1s[FF];
__device__ float g_w2s[FF];
__device__ float g_s1[BB];
__device__ float g_wraw[BB * NN];
__device__ float g_t[BB * KDIM];
// adj single fp16 (written directly by k_adj)
__device__ __half g_adjh[(size_t)BB * CC * FF * FF];  // 67 MB
// A-operand for znx GEMM: per b, 80 rows (64 neighbors, x, 15 pad), fp16 2-digit
__device__ __half g_nxh[(size_t)BB * 80 * KDIM];
__device__ __half g_nxl[(size_t)BB * 80 * KDIM];
// single fp16 Z and W for the big GEMM
__device__ __half g_Zh[(size_t)MPAD * KDIM];
__device__ __half g_Wh[(size_t)ODIM * KDIM];

__device__ __forceinline__ float blockReduce256(float v) {
    __shared__ float sh[8];
    #pragma unroll
    for (int o = 16; o > 0; o >>= 1) v += __shfl_down_sync(0xffffffffu, v, o);
    int lane = threadIdx.x & 31, wid = threadIdx.x >> 5;
    if (lane == 0) sh[wid] = v;
    __syncthreads();
    if (wid == 0) {
        v = (lane < 8) ? sh[lane] : 0.f;
        #pragma unroll
        for (int o = 4; o > 0; o >>= 1) v += __shfl_down_sync(0xffffffffu, v, o);
    }
    return v;
}

// K0: column sums of W1/W2
__global__ void k_wsum(const float* __restrict__ W1, const float* __restrict__ W2) {
    int f = threadIdx.x;
    float a = 0.f, b = 0.f;
    #pragma unroll
    for (int k = 0; k < CC; k++) { a += W1[k * FF + f]; b += W2[k * FF + f]; }
    g_w1s[f] = a; g_w2s[f] = b;
}

// K3: t[b,c,d] = sum_n nb[b,n,c,d] * (s1[b]*wraw[b,n])
__global__ void k_t(const float* __restrict__ nb) {
    int b = blockIdx.x >> 3;
    int r = ((blockIdx.x & 7) << 8) | threadIdx.x;
    __shared__ float sw[NN];
    if (threadIdx.x < NN)
        sw[threadIdx.x] = g_wraw[b * NN + threadIdx.x] * g_s1[b];
    __syncthreads();
    const float* p = nb + (size_t)b * NN * KDIM + r;
    float acc = 0.f;
    #pragma unroll 8
    for (int n = 0; n < NN; n++) acc += p[(size_t)n * KDIM] * sw[n];
    g_t[b * KDIM + r] = acc;
}

// K4: adj[b,c,a,d] = sgnroot(x_a t_d + x_d t_a) / (sum_c |sgnroot| + 1e-7)
// Writes single fp16.
__global__ void k_adj(const float* __restrict__ x) {
    int a = blockIdx.x, b = blockIdx.y;
    __shared__ float sxa[CC], sta[CC];
    int tid = threadIdx.x;
    if (tid < CC)            sxa[tid]      = x[b * KDIM + tid * FF + a];
    else if (tid < 2 * CC)   sta[tid - CC] = g_t[b * KDIM + (tid - CC) * FF + a];
    __syncthreads();
    int d = tid;
    float gg[CC];
    float den = 1e-7f;
    #pragma unroll
    for (int c = 0; c < CC; c++) {
        float xd = x[b * KDIM + c * FF + d];
        float td = g_t[b * KDIM + c * FF + d];
        float fa = sxa[c] * td + xd * sta[c];
        float s  = (fa > 0.f) ? 1.f : ((fa < 0.f) ? -1.f : 0.f);
        float g  = s * sqrtf(fmaxf(fabsf(fa), 1e-8f));
        gg[c] = g;
        den += fabsf(g);
    }
    float inv = 1.f / den;
    size_t base = ((size_t)(b * CC) * FF + a) * FF + d;
    #pragma unroll
    for (int c = 0; c < CC; c++)
        g_adjh[base + (size_t)c * FF * FF] = __float2half_rn(gg[c] * inv);
}

// W -> single fp16
__global__ void k_cvt_W(const float* __restrict__ Wc) {
    size_t row = blockIdx.x;
    int c0 = threadIdx.x * 8;
    const float4* p = (const float4*)(Wc + row * KDIM + c0);
    float4 v0 = p[0], v1 = p[1];
    float vv[8] = {v0.x, v0.y, v0.z, v0.w, v1.x, v1.y, v1.z, v1.w};
    __align__(16) __half h[8];
    #pragma unroll
    for (int i = 0; i < 8; i++) h[i] = __float2half_rn(vv[i]);
    *(uint4*)(g_Wh + row * KDIM + c0) = *(uint4*)&h[0];
}

// Build 80-row A operand (fp16 2-digit) AND fold in the s1 / wraw reductions.
__global__ void k_cvt_nx(const float* __restrict__ x, const float* __restrict__ nb) {
    int r = blockIdx.x, b = blockIdx.y;
    int c0 = threadIdx.x * 8;
    size_t orow = ((size_t)b * 80 + r) * KDIM + c0;
    __align__(16) __half h[8], l[8];
    if (r <= 64) {
        const float* src = (r < 64) ? nb + ((size_t)b * NN + r) * KDIM
                                    : x + (size_t)b * KDIM;
        const float4* p = (const float4*)(src + c0);
        float4 v0 = p[0], v1 = p[1];
        float vv[8] = {v0.x, v0.y, v0.z, v0.w, v1.x, v1.y, v1.z, v1.w};
        #pragma unroll
        for (int i = 0; i < 8; i++) {
            h[i] = __float2half_rn(vv[i]);
            l[i] = __float2half_rn(vv[i] - __half2float(h[i]));
        }
        *(uint4*)(g_nxh + orow) = *(uint4*)&h[0];
        *(uint4*)(g_nxl + orow) = *(uint4*)&l[0];
        // fused attention-sum reductions (replaces k_s1 and k_w)
        const float* ws = (r < 64) ? g_w2s : g_w1s;
        float dot = 0.f;
        #pragma unroll
        for (int i = 0; i < 8; i++) dot += vv[i] * ws[(c0 + i) & (FF - 1)];
        dot = blockReduce256(dot);
        if (threadIdx.x == 0) {
            if (r < 64) g_wraw[b * NN + r] = dot;
            else        g_s1[b] = dot;
        }
    } else {
        #pragma unroll
        for (int i = 0; i < 8; i++) { h[i] = __float2half_rn(0.f); l[i] = h[i]; }
        *(uint4*)(g_nxh + orow) = *(uint4*)&h[0];
        *(uint4*)(g_nxl + orow) = *(uint4*)&l[0];
    }
}

// Zero the pad rows MROWS..MPAD of Zh (read by the big GEMM)
__global__ void k_zero_pad() {
    size_t row = MROWS + blockIdx.x;
    *(uint4*)(g_Zh + row * KDIM + threadIdx.x * 8) = make_uint4(0, 0, 0, 0);
}

// ---------- warp-MMA helpers (sm_80+ PTX only) ----------
__device__ __forceinline__ uint32_t smem_u32(const void* p) {
    uint32_t a;
    asm("{ .reg .u64 t; cvta.to.shared.u64 t, %1; cvt.u32.u64 %0, t; }"
        : "=r"(a) : "l"(p));
    return a;
}
__device__ __forceinline__ void cp16(uint32_t s, const void* g) {
    asm volatile("cp.async.cg.shared.global [%0], [%1], 16;" :: "r"(s), "l"(g) : "memory");
}
__device__ __forceinline__ void ldsm4(uint32_t* r, uint32_t addr) {
    asm volatile("ldmatrix.sync.aligned.m8n8.x4.shared.b16 {%0,%1,%2,%3}, [%4];"
                 : "=r"(r[0]), "=r"(r[1]), "=r"(r[2]), "=r"(r[3]) : "r"(addr));
}
__device__ __forceinline__ void mma16816h(float* c, const uint32_t* a, const uint32_t* b) {
    asm volatile(
        "mma.sync.aligned.m16n8k16.row.col.f32.f16.f16.f32 "
        "{%0,%1,%2,%3}, {%4,%5,%6,%7}, {%8,%9}, {%0,%1,%2,%3};"
        : "+f"(c[0]), "+f"(c[1]), "+f"(c[2]), "+f"(c[3])
        : "r"(a[0]), "r"(a[1]), "r"(a[2]), "r"(a[3]), "r"(b[0]), "r"(b[1]));
}

// ====================== K5: fused zn+zx tensor GEMM ======================
// Per (b,c): Z[n=80, a=256] = (Nh+Nl)[80x256k] @ Ah[a=256 x 256k]^T (adj single).
// 8 warps: each covers full M=80 (5 m16 frags) x N=32. K-chunk 32, 3-stage.
#define ZNST 3
#define ZROWB 80
#define ZA_TILE (80 * ZROWB)       // 6400
#define ZB_TILE (256 * ZROWB)      // 20480
#define ZSTAGE (2 * ZA_TILE + ZB_TILE)  // 33280
#define ZNX_SMEM (ZNST * ZSTAGE)   // 99840

__device__ __forceinline__ void znx_load(char* smbase, int st, int kc,
                                         int tid, int b, int c) {
    uint32_t so = smem_u32(smbase) + st * ZSTAGE;
    int kb = kc << 5;
    #pragma unroll
    for (int t = 0; t < 2; t++) {
        int idx = tid + (t << 8);
        if (idx < 320) {
            int r = idx >> 2, s = idx & 3;
            size_t g = ((size_t)b * 80 + r) * KDIM + c * FF + kb + s * 8;
            uint32_t d = so + r * ZROWB + (s << 4);
            cp16(d, g_nxh + g);
            cp16(d + ZA_TILE, g_nxl + g);
        }
    }
    #pragma unroll
    for (int t = 0; t < 4; t++) {
        int idx = tid + (t << 8);
        int a = idx >> 2, s = idx & 3;
        size_t g = (((size_t)(b * CC + c)) * FF + a) * FF + kb + s * 8;
        cp16(so + 2 * ZA_TILE + a * ZROWB + (s << 4), g_adjh + g);
    }
}

__global__ __launch_bounds__(256, 1) void k_znx() {
    extern __shared__ char sm[];
    uint32_t sbase = smem_u32(sm);
    int tid = threadIdx.x;
    int lane = tid & 31, wid = tid >> 5;
    int c = blockIdx.x, b = blockIdx.y;
    int wn = wid << 5;

    float acc[5][4][4];
    #pragma unroll
    for (int i = 0; i < 5; i++)
        #pragma unroll
        for (int j = 0; j < 4; j++)
            #pragma unroll
            for (int q = 0; q < 4; q++) acc[i][j][q] = 0.f;

    int a_row = ((lane >> 3) & 1) * 8 + (lane & 7);
    int a_kof = (lane >> 4) * 8;
    int b_row = wn + ((lane >> 4) & 1) * 8 + (lane & 7);
    int b_kof = ((lane >> 3) & 1) * 8;

    znx_load(sm, 0, 0, tid, b, c);
    asm volatile("cp.async.commit_group;" ::: "memory");
    znx_load(sm, 1, 1, tid, b, c);
    asm volatile("cp.async.commit_group;" ::: "memory");

    for (int kc = 0; kc < 8; kc++) {
        asm volatile("cp.async.wait_group 1;" ::: "memory");
        __syncthreads();
        if (kc + 2 < 8) znx_load(sm, (kc + 2) % ZNST, kc + 2, tid, b, c);
        asm volatile("cp.async.commit_group;" ::: "memory");

        uint32_t sA  = sbase + (kc % ZNST) * ZSTAGE;
        uint32_t sAl = sA + ZA_TILE;
        uint32_t sB  = sA + 2 * ZA_TILE;
        #pragma unroll
        for (int kk = 0; kk < 2; kk++) {
            int kb = kk << 4;
            uint32_t ah[5][4], al[5][4], bh[2][4];
            uint32_t aofs = a_row * ZROWB + (kb + a_kof) * 2;
            #pragma unroll
            for (int mt = 0; mt < 5; mt++) {
                ldsm4(ah[mt], sA  + aofs + mt * 16 * ZROWB);
                ldsm4(al[mt], sAl + aofs + mt * 16 * ZROWB);
            }
            uint32_t bofs = b_row * ZROWB + (kb + b_kof) * 2;
            #pragma unroll
            for (int np = 0; np < 2; np++)
                ldsm4(bh[np], sB + bofs + np * 16 * ZROWB);
            #pragma unroll
            for (int mt = 0; mt < 5; mt++)
                #pragma unroll
                for (int j = 0; j < 4; j++) {
                    const uint32_t* pbh = &bh[j >> 1][(j & 1) * 2];
                    mma16816h(acc[mt][j], ah[mt], pbh);
                    mma16816h(acc[mt][j], al[mt], pbh);
                }
        }
        __syncthreads();
    }

    // epilogue: rows = n (x at n==64), cols = a; write single fp16 Zh
    #pragma unroll
    for (int mt = 0; mt < 5; mt++) {
        #pragma unroll
        for (int half = 0; half < 2; half++) {
            int r = mt * 16 + (lane >> 2) + half * 8;
            int zr;
            if (r < 64)       zr = 64 + b * NN + r;
            else if (r == 64) zr = b;
            else continue;
            #pragma unroll
            for (int j = 0; j < 4; j++) {
                int col = c * FF + wn + j * 8 + (lane & 3) * 2;
                *(__half2*)(g_Zh + (size_t)zr * KDIM + col) =
                    __halves2half2(__float2half_rn(acc[mt][j][half * 2]),
                                   __float2half_rn(acc[mt][j][half * 2 + 1]));
            }
        }
    }
}

// ====================== K7: big GEMM, single fp16 x single fp16 ======================
// out = Zh(4224x2048) @ Wh^T(2048x2048): 1 MMA per k16 subtile, 5-stage pipeline.
#define NST 5
#define ROWB 80
#define TILE_B (128 * ROWB)
#define STAGE_B (2 * TILE_B)          // Zh, Wh
#define GEMM_SMEM (NST * STAGE_B)     // 102400

__device__ __forceinline__ void g_load_stage(char* smembase, int st, int kc,
                                             int tid, int m0, int n0) {
    uint32_t so_base = smem_u32(smembase) + st * STAGE_B;
    #pragma unroll
    for (int t = 0; t < 2; t++) {
        int idx = tid + (t << 8);
        int row = idx >> 2, seg = idx & 3;
        size_t gA = (size_t)(m0 + row) * KDIM + (kc << 5) + (seg << 3);
        size_t gB = (size_t)(n0 + row) * KDIM + (kc << 5) + (seg << 3);
        uint32_t so = so_base + row * ROWB + (seg << 4);
        cp16(so,          g_Zh + gA);
        cp16(so + TILE_B, g_Wh + gB);
    }
}

__global__ __launch_bounds__(256, 1) void k_gemm_mma(float* __restrict__ out) {
    extern __shared__ char sm[];
    uint32_t sbase = smem_u32(sm);
    int tid = threadIdx.x;
    int lane = tid & 31, wid = tid >> 5;
    int m0 = blockIdx.y << 7, n0 = blockIdx.x << 7;
    int wm = (wid >> 2) << 6;
    int wn = (wid & 3) << 5;

    float c[4][4][4];
    #pragma unroll
    for (int i = 0; i < 4; i++)
        #pragma unroll
        for (int j = 0; j < 4; j++)
            #pragma unroll
            for (int q = 0; q < 4; q++) c[i][j][q] = 0.f;

    int a_row = wm + ((lane >> 3) & 1) * 8 + (lane & 7);
    int a_kof = (lane >> 4) * 8;
    int b_row = wn + ((lane >> 4) & 1) * 8 + (lane & 7);
    int b_kof = ((lane >> 3) & 1) * 8;

    #pragma unroll
    for (int st = 0; st < 4; st++) {
        g_load_stage(sm, st, st, tid, m0, n0);
        asm volatile("cp.async.commit_group;" ::: "memory");
    }

    for (int kc = 0; kc < 64; kc++) {
        asm volatile("cp.async.wait_group 3;" ::: "memory");
        __syncthreads();
        if (kc + 4 < 64) g_load_stage(sm, (kc + 4) % NST, kc + 4, tid, m0, n0);
        asm volatile("cp.async.commit_group;" ::: "memory");

        uint32_t sA = sbase + (kc % NST) * STAGE_B;
        uint32_t sB = sA + TILE_B;
        #pragma unroll
        for (int kk = 0; kk < 2; kk++) {
            int kb = kk << 4;
            uint32_t ah[4][4], bh[2][4];
            uint32_t aofs = a_row * ROWB + (kb + a_kof) * 2;
            #pragma unroll
            for (int mt = 0; mt < 4; mt++)
                ldsm4(ah[mt], sA + aofs + mt * 16 * ROWB);
            uint32_t bofs = b_row * ROWB + (kb + b_kof) * 2;
            #pragma unroll
            for (int np = 0; np < 2; np++)
                ldsm4(bh[np], sB + bofs + np * 16 * ROWB);
            #pragma unroll
            for (int mt = 0; mt < 4; mt++)
                #pragma unroll
                for (int j = 0; j < 4; j++)
                    mma16816h(c[mt][j], ah[mt], &bh[j >> 1][(j & 1) * 2]);
        }
        __syncthreads();
    }

    #pragma unroll
    for (int mt = 0; mt < 4; mt++) {
        int r0 = m0 + wm + mt * 16 + (lane >> 2);
        #pragma unroll
        for (int j = 0; j < 4; j++) {
            int col = n0 + wn + j * 8 + (lane & 3) * 2;
            if (r0 < MROWS)
                *(float2*)(out + (size_t)r0 * ODIM + col) =
                    make_float2(c[mt][j][0], c[mt][j][1]);
            if (r0 + 8 < MROWS)
                *(float2*)(out + (size_t)(r0 + 8) * ODIM + col) =
                    make_float2(c[mt][j][2], c[mt][j][3]);
        }
    }
}

extern "C" void kernel_launch(void* const* d_in, const int* in_sizes, int n_in,
                              void* d_out, int out_size) {
    const float* x  = (const float*)d_in[0];  // (64,8,256)
    const float* nb = (const float*)d_in[1];  // (64,64,8,256)
    const float* W1 = (const float*)d_in[2];  // (8,256)
    const float* W2 = (const float*)d_in[3];  // (8,256)
    const float* Wc = (const float*)d_in[4];  // (2048,8,256)
    float* out = (float*)d_out;

    static bool attr_set = false;
    if (!attr_set) {
        cudaFuncSetAttribute(k_gemm_mma, cudaFuncAttributeMaxDynamicSharedMemorySize,
                             GEMM_SMEM);
        cudaFuncSetAttribute(k_znx, cudaFuncAttributeMaxDynamicSharedMemorySize,
                             ZNX_SMEM);
        attr_set = true;
    }

    k_wsum<<<1, 256>>>(W1, W2);
    k_cvt_W<<<ODIM, 256>>>(Wc);
    k_cvt_nx<<<dim3(80, BB), 256>>>(x, nb);
    k_t<<<512, 256>>>(nb);
    k_adj<<<dim3(FF, BB), 256>>>(x);
    k_zero_pad<<<MPAD - MROWS, 256>>>();
    k_znx<<<dim3(CC, BB), 256, ZNX_SMEM>>>();
    k_gemm_mma<<<dim3(16, 33), 256, GEMM_SMEM>>>(out);
}

// round 9
// speedup vs baseline: 6.0760x; 1.0913x over previous
#include <cuda_runtime.h>
#include <cuda_bf16.h>
#include <cuda_fp16.h>
#include <cstdint>

// Problem constants
#define BB 64
#define NN 64
#define CC 8
#define FF 256
#define KDIM 2048   // C*F
#define ODIM 2048   // OC*OF
#define MROWS 4160  // B + B*N rows of Z
#define MPAD 4224   // padded to 33*128

// Scratch (device globals; no dynamic allocation allowed)
__device__ float g_w1s[FF];
__device__ float g_w2s[FF];
__device__ float g_s1[BB];
__device__ float g_wraw[BB * NN];
__device__ float g_t[BB * KDIM];
// adj single fp16 (written directly by k_adj)
__device__ __half g_adjh[(size_t)BB * CC * FF * FF];  // 67 MB
// A-operand for znx GEMM: per b, 80 rows (64 neighbors, x, 15 pad), single fp16
__device__ __half g_nxh[(size_t)BB * 80 * KDIM];
// single fp16 Z and W for the big GEMM
__device__ __half g_Zh[(size_t)MPAD * KDIM];
__device__ __half g_Wh[(size_t)ODIM * KDIM];

__device__ __forceinline__ float blockReduce256(float v) {
    __shared__ float sh[8];
    #pragma unroll
    for (int o = 16; o > 0; o >>= 1) v += __shfl_down_sync(0xffffffffu, v, o);
    int lane = threadIdx.x & 31, wid = threadIdx.x >> 5;
    if (lane == 0) sh[wid] = v;
    __syncthreads();
    if (wid == 0) {
        v = (lane < 8) ? sh[lane] : 0.f;
        #pragma unroll
        for (int o = 4; o > 0; o >>= 1) v += __shfl_down_sync(0xffffffffu, v, o);
    }
    return v;
}

// K0: column sums of W1/W2
__global__ void k_wsum(const float* __restrict__ W1, const float* __restrict__ W2) {
    int f = threadIdx.x;
    float a = 0.f, b = 0.f;
    #pragma unroll
    for (int k = 0; k < CC; k++) { a += W1[k * FF + f]; b += W2[k * FF + f]; }
    g_w1s[f] = a; g_w2s[f] = b;
}

// K3: t[b,c,d] = sum_n nxh[b,n,c,d] * (s1[b]*wraw[b,n])  (fp16 source, fp32 accum)
__global__ void k_t() {
    int b = blockIdx.x >> 3;
    int r = ((blockIdx.x & 7) << 8) | threadIdx.x;
    __shared__ float sw[NN];
    if (threadIdx.x < NN)
        sw[threadIdx.x] = g_wraw[b * NN + threadIdx.x] * g_s1[b];
    __syncthreads();
    const __half* p = g_nxh + (size_t)b * 80 * KDIM + r;
    float acc = 0.f;
    #pragma unroll 8
    for (int n = 0; n < NN; n++) acc += __half2float(p[(size_t)n * KDIM]) * sw[n];
    g_t[b * KDIM + r] = acc;
}

// K4: adj[b,c,a,d] = sgnroot(x_a t_d + x_d t_a) / (sum_c |sgnroot| + 1e-7)
// Writes single fp16.
__global__ void k_adj(const float* __restrict__ x) {
    int a = blockIdx.x, b = blockIdx.y;
    __shared__ float sxa[CC], sta[CC];
    int tid = threadIdx.x;
    if (tid < CC)            sxa[tid]      = x[b * KDIM + tid * FF + a];
    else if (tid < 2 * CC)   sta[tid - CC] = g_t[b * KDIM + (tid - CC) * FF + a];
    __syncthreads();
    int d = tid;
    float gg[CC];
    float den = 1e-7f;
    #pragma unroll
    for (int c = 0; c < CC; c++) {
        float xd = x[b * KDIM + c * FF + d];
        float td = g_t[b * KDIM + c * FF + d];
        float fa = sxa[c] * td + xd * sta[c];
        float s  = (fa > 0.f) ? 1.f : ((fa < 0.f) ? -1.f : 0.f);
        float g  = s * sqrtf(fmaxf(fabsf(fa), 1e-8f));
        gg[c] = g;
        den += fabsf(g);
    }
    float inv = 1.f / den;
    size_t base = ((size_t)(b * CC) * FF + a) * FF + d;
    #pragma unroll
    for (int c = 0; c < CC; c++)
        g_adjh[base + (size_t)c * FF * FF] = __float2half_rn(gg[c] * inv);
}

// W -> single fp16; trailing 64 blocks zero the Zh pad rows
__global__ void k_cvt_W(const float* __restrict__ Wc) {
    size_t bid = blockIdx.x;
    int c0 = threadIdx.x * 8;
    if (bid < ODIM) {
        const float4* p = (const float4*)(Wc + bid * KDIM + c0);
        float4 v0 = p[0], v1 = p[1];
        float vv[8] = {v0.x, v0.y, v0.z, v0.w, v1.x, v1.y, v1.z, v1.w};
        __align__(16) __half h[8];
        #pragma unroll
        for (int i = 0; i < 8; i++) h[i] = __float2half_rn(vv[i]);
        *(uint4*)(g_Wh + bid * KDIM + c0) = *(uint4*)&h[0];
    } else {
        size_t row = MROWS + (bid - ODIM);
        *(uint4*)(g_Zh + row * KDIM + c0) = make_uint4(0, 0, 0, 0);
    }
}

// Build 80-row A operand (single fp16) AND fold in the s1 / wraw reductions.
__global__ void k_cvt_nx(const float* __restrict__ x, const float* __restrict__ nb) {
    int r = blockIdx.x, b = blockIdx.y;
    int c0 = threadIdx.x * 8;
    size_t orow = ((size_t)b * 80 + r) * KDIM + c0;
    __align__(16) __half h[8];
    if (r <= 64) {
        const float* src = (r < 64) ? nb + ((size_t)b * NN + r) * KDIM
                                    : x + (size_t)b * KDIM;
        const float4* p = (const float4*)(src + c0);
        float4 v0 = p[0], v1 = p[1];
        float vv[8] = {v0.x, v0.y, v0.z, v0.w, v1.x, v1.y, v1.z, v1.w};
        #pragma unroll
        for (int i = 0; i < 8; i++) h[i] = __float2half_rn(vv[i]);
        *(uint4*)(g_nxh + orow) = *(uint4*)&h[0];
        // fused attention-sum reductions (replaces k_s1 and k_w)
        const float* ws = (r < 64) ? g_w2s : g_w1s;
        float dot = 0.f;
        #pragma unroll
        for (int i = 0; i < 8; i++) dot += vv[i] * ws[(c0 + i) & (FF - 1)];
        dot = blockReduce256(dot);
        if (threadIdx.x == 0) {
            if (r < 64) g_wraw[b * NN + r] = dot;
            else        g_s1[b] = dot;
        }
    } else {
        #pragma unroll
        for (int i = 0; i < 8; i++) h[i] = __float2half_rn(0.f);
        *(uint4*)(g_nxh + orow) = *(uint4*)&h[0];
    }
}

// ---------- warp-MMA helpers (sm_80+ PTX only) ----------
__device__ __forceinline__ uint32_t smem_u32(const void* p) {
    uint32_t a;
    asm("{ .reg .u64 t; cvta.to.shared.u64 t, %1; cvt.u32.u64 %0, t; }"
        : "=r"(a) : "l"(p));
    return a;
}
__device__ __forceinline__ void cp16(uint32_t s, const void* g) {
    asm volatile("cp.async.cg.shared.global [%0], [%1], 16;" :: "r"(s), "l"(g) : "memory");
}
__device__ __forceinline__ void ldsm4(uint32_t* r, uint32_t addr) {
    asm volatile("ldmatrix.sync.aligned.m8n8.x4.shared.b16 {%0,%1,%2,%3}, [%4];"
                 : "=r"(r[0]), "=r"(r[1]), "=r"(r[2]), "=r"(r[3]) : "r"(addr));
}
__device__ __forceinline__ void mma16816h(float* c, const uint32_t* a, const uint32_t* b) {
    asm volatile(
        "mma.sync.aligned.m16n8k16.row.col.f32.f16.f16.f32 "
        "{%0,%1,%2,%3}, {%4,%5,%6,%7}, {%8,%9}, {%0,%1,%2,%3};"
        : "+f"(c[0]), "+f"(c[1]), "+f"(c[2]), "+f"(c[3])
        : "r"(a[0]), "r"(a[1]), "r"(a[2]), "r"(a[3]), "r"(b[0]), "r"(b[1]));
}

// ====================== K5: fused zn+zx tensor GEMM ======================
// Per (b,c): Z[n=80, a=256] = Nh[80x256k] @ Ah[a=256 x 256k]^T  (both single fp16)
// 8 warps: each covers full M=80 (5 m16 frags) x N=32. K-chunk 32, 3-stage.
#define ZNST 3
#define ZROWB 80
#define ZA_TILE (80 * ZROWB)       // 6400
#define ZB_TILE (256 * ZROWB)      // 20480
#define ZSTAGE (ZA_TILE + ZB_TILE) // 26880
#define ZNX_SMEM (ZNST * ZSTAGE)   // 80640

__device__ __forceinline__ void znx_load(char* smbase, int st, int kc,
                                         int tid, int b, int c) {
    uint32_t so = smem_u32(smbase) + st * ZSTAGE;
    int kb = kc << 5;
    {
        int idx = tid;              // 80*4 = 320 A-loads; threads 0..255 do 1, 64 do 2
        int r = idx >> 2, s = idx & 3;
        size_t g = ((size_t)b * 80 + r) * KDIM + c * FF + kb + s * 8;
        cp16(so + r * ZROWB + (s << 4), g_nxh + g);
        if (tid < 64) {
            int idx2 = tid + 256;
            int r2 = idx2 >> 2, s2 = idx2 & 3;
            size_t g2 = ((size_t)b * 80 + r2) * KDIM + c * FF + kb + s2 * 8;
            cp16(so + r2 * ZROWB + (s2 << 4), g_nxh + g2);
        }
    }
    #pragma unroll
    for (int t = 0; t < 4; t++) {
        int idx = tid + (t << 8);
        int a = idx >> 2, s = idx & 3;
        size_t g = (((size_t)(b * CC + c)) * FF + a) * FF + kb + s * 8;
        cp16(so + ZA_TILE + a * ZROWB + (s << 4), g_adjh + g);
    }
}

__global__ __launch_bounds__(256, 1) void k_znx() {
    extern __shared__ char sm[];
    uint32_t sbase = smem_u32(sm);
    int tid = threadIdx.x;
    int lane = tid & 31, wid = tid >> 5;
    int c = blockIdx.x, b = blockIdx.y;
    int wn = wid << 5;

    float acc[5][4][4];
    #pragma unroll
    for (int i = 0; i < 5; i++)
        #pragma unroll
        for (int j = 0; j < 4; j++)
            #pragma unroll
            for (int q = 0; q < 4; q++) acc[i][j][q] = 0.f;

    int a_row = ((lane >> 3) & 1) * 8 + (lane & 7);
    int a_kof = (lane >> 4) * 8;
    int b_row = wn + ((lane >> 4) & 1) * 8 + (lane & 7);
    int b_kof = ((lane >> 3) & 1) * 8;

    znx_load(sm, 0, 0, tid, b, c);
    asm volatile("cp.async.commit_group;" ::: "memory");
    znx_load(sm, 1, 1, tid, b, c);
    asm volatile("cp.async.commit_group;" ::: "memory");

    for (int kc = 0; kc < 8; kc++) {
        asm volatile("cp.async.wait_group 1;" ::: "memory");
        __syncthreads();
        if (kc + 2 < 8) znx_load(sm, (kc + 2) % ZNST, kc + 2, tid, b, c);
        asm volatile("cp.async.commit_group;" ::: "memory");

        uint32_t sA = sbase + (kc % ZNST) * ZSTAGE;
        uint32_t sB = sA + ZA_TILE;
        #pragma unroll
        for (int kk = 0; kk < 2; kk++) {
            int kb = kk << 4;
            uint32_t ah[5][4], bh[2][4];
            uint32_t aofs = a_row * ZROWB + (kb + a_kof) * 2;
            #pragma unroll
            for (int mt = 0; mt < 5; mt++)
                ldsm4(ah[mt], sA + aofs + mt * 16 * ZROWB);
            uint32_t bofs = b_row * ZROWB + (kb + b_kof) * 2;
            #pragma unroll
            for (int np = 0; np < 2; np++)
                ldsm4(bh[np], sB + bofs + np * 16 * ZROWB);
            #pragma unroll
            for (int mt = 0; mt < 5; mt++)
                #pragma unroll
                for (int j = 0; j < 4; j++)
                    mma16816h(acc[mt][j], ah[mt], &bh[j >> 1][(j & 1) * 2]);
        }
        __syncthreads();
    }

    // epilogue: rows = n (x at n==64), cols = a; write single fp16 Zh
    #pragma unroll
    for (int mt = 0; mt < 5; mt++) {
        #pragma unroll
        for (int half = 0; half < 2; half++) {
            int r = mt * 16 + (lane >> 2) + half * 8;
            int zr;
            if (r < 64)       zr = 64 + b * NN + r;
            else if (r == 64) zr = b;
            else continue;
            #pragma unroll
            for (int j = 0; j < 4; j++) {
                int col = c * FF + wn + j * 8 + (lane & 3) * 2;
                *(__half2*)(g_Zh + (size_t)zr * KDIM + col) =
                    __halves2half2(__float2half_rn(acc[mt][j][half * 2]),
                                   __float2half_rn(acc[mt][j][half * 2 + 1]));
            }
        }
    }
}

// ====================== K7: big GEMM, single fp16 x single fp16 ======================
// out = Zh(4224x2048) @ Wh^T(2048x2048): 1 MMA per k16 subtile, 5-stage pipeline.
#define NST 5
#define ROWB 80
#define TILE_B (128 * ROWB)
#define STAGE_B (2 * TILE_B)          // Zh, Wh
#define GEMM_SMEM (NST * STAGE_B)     // 102400

__device__ __forceinline__ void g_load_stage(char* smembase, int st, int kc,
                                             int tid, int m0, int n0) {
    uint32_t so_base = smem_u32(smembase) + st * STAGE_B;
    #pragma unroll
    for (int t = 0; t < 2; t++) {
        int idx = tid + (t << 8);
        int row = idx >> 2, seg = idx & 3;
        size_t gA = (size_t)(m0 + row) * KDIM + (kc << 5) + (seg << 3);
        size_t gB = (size_t)(n0 + row) * KDIM + (kc << 5) + (seg << 3);
        uint32_t so = so_base + row * ROWB + (seg << 4);
        cp16(so,          g_Zh + gA);
        cp16(so + TILE_B, g_Wh + gB);
    }
}

__global__ __launch_bounds__(256, 1) void k_gemm_mma(float* __restrict__ out) {
    extern __shared__ char sm[];
    uint32_t sbase = smem_u32(sm);
    int tid = threadIdx.x;
    int lane = tid & 31, wid = tid >> 5;
    int m0 = blockIdx.y << 7, n0 = blockIdx.x << 7;
    int wm = (wid >> 2) << 6;
    int wn = (wid & 3) << 5;

    float c[4][4][4];
    #pragma unroll
    for (int i = 0; i < 4; i++)
        #pragma unroll
        for (int j = 0; j < 4; j++)
            #pragma unroll
            for (int q = 0; q < 4; q++) c[i][j][q] = 0.f;

    int a_row = wm + ((lane >> 3) & 1) * 8 + (lane & 7);
    int a_kof = (lane >> 4) * 8;
    int b_row = wn + ((lane >> 4) & 1) * 8 + (lane & 7);
    int b_kof = ((lane >> 3) & 1) * 8;

    #pragma unroll
    for (int st = 0; st < 4; st++) {
        g_load_stage(sm, st, st, tid, m0, n0);
        asm volatile("cp.async.commit_group;" ::: "memory");
    }

    for (int kc = 0; kc < 64; kc++) {
        asm volatile("cp.async.wait_group 3;" ::: "memory");
        __syncthreads();
        if (kc + 4 < 64) g_load_stage(sm, (kc + 4) % NST, kc + 4, tid, m0, n0);
        asm volatile("cp.async.commit_group;" ::: "memory");

        uint32_t sA = sbase + (kc % NST) * STAGE_B;
        uint32_t sB = sA + TILE_B;
        #pragma unroll
        for (int kk = 0; kk < 2; kk++) {
            int kb = kk << 4;
            uint32_t ah[4][4], bh[2][4];
            uint32_t aofs = a_row * ROWB + (kb + a_kof) * 2;
            #pragma unroll
            for (int mt = 0; mt < 4; mt++)
                ldsm4(ah[mt], sA + aofs + mt * 16 * ROWB);
            uint32_t bofs = b_row * ROWB + (kb + b_kof) * 2;
            #pragma unroll
            for (int np = 0; np < 2; np++)
                ldsm4(bh[np], sB + bofs + np * 16 * ROWB);
            #pragma unroll
            for (int mt = 0; mt < 4; mt++)
                #pragma unroll
                for (int j = 0; j < 4; j++)
                    mma16816h(c[mt][j], ah[mt], &bh[j >> 1][(j & 1) * 2]);
        }
        __syncthreads();
    }

    #pragma unroll
    for (int mt = 0; mt < 4; mt++) {
        int r0 = m0 + wm + mt * 16 + (lane >> 2);
        #pragma unroll
        for (int j = 0; j < 4; j++) {
            int col = n0 + wn + j * 8 + (lane & 3) * 2;
            if (r0 < MROWS)
                *(float2*)(out + (size_t)r0 * ODIM + col) =
                    make_float2(c[mt][j][0], c[mt][j][1]);
            if (r0 + 8 < MROWS)
                *(float2*)(out + (size_t)(r0 + 8) * ODIM + col) =
                    make_float2(c[mt][j][2], c[mt][j][3]);
        }
    }
}

extern "C" void kernel_launch(void* const* d_in, const int* in_sizes, int n_in,
                              void* d_out, int out_size) {
    const float* x  = (const float*)d_in[0];  // (64,8,256)
    const float* nb = (const float*)d_in[1];  // (64,64,8,256)
    const float* W1 = (const float*)d_in[2];  // (8,256)
    const float* W2 = (const float*)d_in[3];  // (8,256)
    const float* Wc = (const float*)d_in[4];  // (2048,8,256)
    float* out = (float*)d_out;

    static bool attr_set = false;
    if (!attr_set) {
        cudaFuncSetAttribute(k_gemm_mma, cudaFuncAttributeMaxDynamicSharedMemorySize,
                             GEMM_SMEM);
        cudaFuncSetAttribute(k_znx, cudaFuncAttributeMaxDynamicSharedMemorySize,
                             ZNX_SMEM);
        attr_set = true;
    }

    k_wsum<<<1, 256>>>(W1, W2);
    k_cvt_W<<<ODIM + (MPAD - MROWS), 256>>>(Wc);
    k_cvt_nx<<<dim3(80, BB), 256>>>(x, nb);
    k_t<<<512, 256>>>();
    k_adj<<<dim3(FF, BB), 256>>>(x);
    k_znx<<<dim3(CC, BB), 256, ZNX_SMEM>>>();
    k_gemm_mma<<<dim3(16, 33), 256, GEMM_SMEM>>>(out);
}

// round 11
// speedup vs baseline: 6.2863x; 1.0346x over previous
#include <cuda_runtime.h>
#include <cuda_bf16.h>
#include <cuda_fp16.h>
#include <cstdint>

// Problem constants
#define BB 64
#define NN 64
#define CC 8
#define FF 256
#define KDIM 2048   // C*F
#define ODIM 2048   // OC*OF
#define MROWS 4160  // B + B*N rows of Z
#define MPAD 4224   // padded to 33*128

// Scratch (device globals; no dynamic allocation allowed)
__device__ float g_w1s[FF];
__device__ float g_w2s[FF];
__device__ float g_s1[BB];
__device__ float g_wraw[BB * NN];
__device__ float g_t[BB * KDIM];
// adj single fp16 (written directly by k_adj)
__device__ __half g_adjh[(size_t)BB * CC * FF * FF];  // 67 MB
// A-operand for znx GEMM: per b, 80 rows (64 neighbors, x, 15 pad), single fp16
__device__ __half g_nxh[(size_t)BB * 80 * KDIM];
// single fp16 Z and W for the big GEMM
__device__ __half g_Zh[(size_t)MPAD * KDIM];
__device__ __half g_Wh[(size_t)ODIM * KDIM];

__device__ __forceinline__ float blockReduce256(float v) {
    __shared__ float sh[8];
    #pragma unroll
    for (int o = 16; o > 0; o >>= 1) v += __shfl_down_sync(0xffffffffu, v, o);
    int lane = threadIdx.x & 31, wid = threadIdx.x >> 5;
    if (lane == 0) sh[wid] = v;
    __syncthreads();
    if (wid == 0) {
        v = (lane < 8) ? sh[lane] : 0.f;
        #pragma unroll
        for (int o = 4; o > 0; o >>= 1) v += __shfl_down_sync(0xffffffffu, v, o);
    }
    return v;
}

// K0: column sums of W1/W2
__global__ void k_wsum(const float* __restrict__ W1, const float* __restrict__ W2) {
    int f = threadIdx.x;
    float a = 0.f, b = 0.f;
    #pragma unroll
    for (int k = 0; k < CC; k++) { a += W1[k * FF + f]; b += W2[k * FF + f]; }
    g_w1s[f] = a; g_w2s[f] = b;
}

// K1 (merged): cvt_nx (blocks 0..5119) + cvt_W (5120..7167) + Zh pad zero (7168..7231)
#define NB_NX   (80 * BB)             // 5120
#define NB_PREP (NB_NX + ODIM + (MPAD - MROWS))

__global__ void k_prep(const float* __restrict__ x, const float* __restrict__ nb,
                       const float* __restrict__ Wc) {
    int bid = blockIdx.x;
    int c0 = threadIdx.x * 8;
    if (bid < NB_NX) {
        // ---- cvt_nx: build 80-row A operand + fused s1/wraw reductions ----
        int r = bid % 80, b = bid / 80;
        size_t orow = ((size_t)b * 80 + r) * KDIM + c0;
        __align__(16) __half h[8];
        if (r <= 64) {
            const float* src = (r < 64) ? nb + ((size_t)b * NN + r) * KDIM
                                        : x + (size_t)b * KDIM;
            const float4* p = (const float4*)(src + c0);
            float4 v0 = p[0], v1 = p[1];
            float vv[8] = {v0.x, v0.y, v0.z, v0.w, v1.x, v1.y, v1.z, v1.w};
            #pragma unroll
            for (int i = 0; i < 8; i++) h[i] = __float2half_rn(vv[i]);
            *(uint4*)(g_nxh + orow) = *(uint4*)&h[0];
            const float* ws = (r < 64) ? g_w2s : g_w1s;
            float dot = 0.f;
            #pragma unroll
            for (int i = 0; i < 8; i++) dot += vv[i] * ws[(c0 + i) & (FF - 1)];
            dot = blockReduce256(dot);
            if (threadIdx.x == 0) {
                if (r < 64) g_wraw[b * NN + r] = dot;
                else        g_s1[b] = dot;
            }
        } else {
            #pragma unroll
            for (int i = 0; i < 8; i++) h[i] = __float2half_rn(0.f);
            *(uint4*)(g_nxh + orow) = *(uint4*)&h[0];
        }
    } else if (bid < NB_NX + ODIM) {
        // ---- cvt_W: W -> single fp16 ----
        size_t row = bid - NB_NX;
        const float4* p = (const float4*)(Wc + row * KDIM + c0);
        float4 v0 = p[0], v1 = p[1];
        float vv[8] = {v0.x, v0.y, v0.z, v0.w, v1.x, v1.y, v1.z, v1.w};
        __align__(16) __half h[8];
        #pragma unroll
        for (int i = 0; i < 8; i++) h[i] = __float2half_rn(vv[i]);
        *(uint4*)(g_Wh + row * KDIM + c0) = *(uint4*)&h[0];
    } else {
        // ---- zero Zh pad rows ----
        size_t row = MROWS + (bid - NB_NX - ODIM);
        *(uint4*)(g_Zh + row * KDIM + c0) = make_uint4(0, 0, 0, 0);
    }
}

// K3: t[b,c,d] = sum_n nxh[b,n,c,d] * (s1[b]*wraw[b,n]); half2 vectorized
__global__ void k_t() {
    int b = blockIdx.x >> 2;
    int r0 = ((blockIdx.x & 3) << 9) | (threadIdx.x << 1);
    __shared__ float sw[NN];
    if (threadIdx.x < NN)
        sw[threadIdx.x] = g_wraw[b * NN + threadIdx.x] * g_s1[b];
    __syncthreads();
    const __half2* p = (const __half2*)(g_nxh + (size_t)b * 80 * KDIM + r0);
    float2 acc = make_float2(0.f, 0.f);
    #pragma unroll 8
    for (int n = 0; n < NN; n++) {
        float2 f = __half22float2(p[(size_t)n * (KDIM / 2)]);
        acc.x += f.x * sw[n];
        acc.y += f.y * sw[n];
    }
    *(float2*)(g_t + (size_t)b * KDIM + r0) = acc;
}

// K4: adj[b,c,a,d] = sgnroot(x_a t_d + x_d t_a) / (sum_c |sgnroot| + 1e-7)
// Vectorized: block = (4 a's, b); each thread: 4 consecutive d x 8 c, STG.64 writes.
__global__ void k_adj(const float* __restrict__ x) {
    int a0 = blockIdx.x << 2, b = blockIdx.y;
    __shared__ float sxa[CC][4], sta[CC][4];
    int t = threadIdx.x;
    if (t < 32)      sxa[t >> 2][t & 3] = x[b * KDIM + (t >> 2) * FF + a0 + (t & 3)];
    else if (t < 64) {
        int q = t - 32;
        sta[q >> 2][q & 3] = g_t[b * KDIM + (q >> 2) * FF + a0 + (q & 3)];
    }
    __syncthreads();
    int al = t >> 6;            // 0..3 -> which a in the group
    int d0 = (t & 63) << 2;     // 0..252, 4 d's per thread
    float gg[CC][4];
    float den[4] = {1e-7f, 1e-7f, 1e-7f, 1e-7f};
    #pragma unroll
    for (int c = 0; c < CC; c++) {
        float xa = sxa[c][al], ta = sta[c][al];
        float4 xd = *(const float4*)(x + b * KDIM + c * FF + d0);
        float4 td = *(const float4*)(g_t + b * KDIM + c * FF + d0);
        float fv[4] = {xa * td.x + xd.x * ta, xa * td.y + xd.y * ta,
                       xa * td.z + xd.z * ta, xa * td.w + xd.w * ta};
        #pragma unroll
        for (int i = 0; i < 4; i++) {
            float fa = fv[i];
            float s = (fa > 0.f) ? 1.f : ((fa < 0.f) ? -1.f : 0.f);
            float g = s * sqrtf(fmaxf(fabsf(fa), 1e-8f));
            gg[c][i] = g;
            den[i] += fabsf(g);
        }
    }
    float inv[4];
    #pragma unroll
    for (int i = 0; i < 4; i++) inv[i] = 1.f / den[i];
    int a = a0 + al;
    #pragma unroll
    for (int c = 0; c < CC; c++) {
        __align__(8) __half h4[4];
        #pragma unroll
        for (int i = 0; i < 4; i++) h4[i] = __float2half_rn(gg[c][i] * inv[i]);
        *(uint2*)(g_adjh + (((size_t)(b * CC + c) * FF + a) * FF + d0)) = *(uint2*)h4;
    }
}

// ---------- warp-MMA helpers (sm_80+ PTX only) ----------
__device__ __forceinline__ uint32_t smem_u32(const void* p) {
    uint32_t a;
    asm("{ .reg .u64 t; cvta.to.shared.u64 t, %1; cvt.u32.u64 %0, t; }"
        : "=r"(a) : "l"(p));
    return a;
}
__device__ __forceinline__ void cp16(uint32_t s, const void* g) {
    asm volatile("cp.async.cg.shared.global [%0], [%1], 16;" :: "r"(s), "l"(g) : "memory");
}
__device__ __forceinline__ void ldsm4(uint32_t* r, uint32_t addr) {
    asm volatile("ldmatrix.sync.aligned.m8n8.x4.shared.b16 {%0,%1,%2,%3}, [%4];"
                 : "=r"(r[0]), "=r"(r[1]), "=r"(r[2]), "=r"(r[3]) : "r"(addr));
}
__device__ __forceinline__ void mma16816h(float* c, const uint32_t* a, const uint32_t* b) {
    asm volatile(
        "mma.sync.aligned.m16n8k16.row.col.f32.f16.f16.f32 "
        "{%0,%1,%2,%3}, {%4,%5,%6,%7}, {%8,%9}, {%0,%1,%2,%3};"
        : "+f"(c[0]), "+f"(c[1]), "+f"(c[2]), "+f"(c[3])
        : "r"(a[0]), "r"(a[1]), "r"(a[2]), "r"(a[3]), "r"(b[0]), "r"(b[1]));
}

// ====================== K5: fused zn+zx tensor GEMM ======================
// Per (b,c): Z[n=80, a=256] = Nh[80x256k] @ Ah[a=256 x 256k]^T  (both single fp16)
// 8 warps: each covers full M=80 (5 m16 frags) x N=32. K-chunk 32, 3-stage.
#define ZNST 3
#define ZROWB 80
#define ZA_TILE (80 * ZROWB)       // 6400
#define ZB_TILE (256 * ZROWB)      // 20480
#define ZSTAGE (ZA_TILE + ZB_TILE) // 26880
#define ZNX_SMEM (ZNST * ZSTAGE)   // 80640

__device__ __forceinline__ void znx_load(char* smbase, int st, int kc,
                                         int tid, int b, int c) {
    uint32_t so = smem_u32(smbase) + st * ZSTAGE;
    int kb = kc << 5;
    {
        int idx = tid;              // 80*4 = 320 A-loads; threads 0..255 do 1, 64 do 2
        int r = idx >> 2, s = idx & 3;
        size_t g = ((size_t)b * 80 + r) * KDIM + c * FF + kb + s * 8;
        cp16(so + r * ZROWB + (s << 4), g_nxh + g);
        if (tid < 64) {
            int idx2 = tid + 256;
            int r2 = idx2 >> 2, s2 = idx2 & 3;
            size_t g2 = ((size_t)b * 80 + r2) * KDIM + c * FF + kb + s2 * 8;
            cp16(so + r2 * ZROWB + (s2 << 4), g_nxh + g2);
        }
    }
    #pragma unroll
    for (int t = 0; t < 4; t++) {
        int idx = tid + (t << 8);
        int a = idx >> 2, s = idx & 3;
        size_t g = (((size_t)(b * CC + c)) * FF + a) * FF + kb + s * 8;
        cp16(so + ZA_TILE + a * ZROWB + (s << 4), g_adjh + g);
    }
}

__global__ __launch_bounds__(256, 1) void k_znx() {
    extern __shared__ char sm[];
    uint32_t sbase = smem_u32(sm);
    int tid = threadIdx.x;
    int lane = tid & 31, wid = tid >> 5;
    int c = blockIdx.x, b = blockIdx.y;
    int wn = wid << 5;

    float acc[5][4][4];
    #pragma unroll
    for (int i = 0; i < 5; i++)
        #pragma unroll
        for (int j = 0; j < 4; j++)
            #pragma unroll
            for (int q = 0; q < 4; q++) acc[i][j][q] = 0.f;

    int a_row = ((lane >> 3) & 1) * 8 + (lane & 7);
    int a_kof = (lane >> 4) * 8;
    int b_row = wn + ((lane >> 4) & 1) * 8 + (lane & 7);
    int b_kof = ((lane >> 3) & 1) * 8;

    znx_load(sm, 0, 0, tid, b, c);
    asm volatile("cp.async.commit_group;" ::: "memory");
    znx_load(sm, 1, 1, tid, b, c);
    asm volatile("cp.async.commit_group;" ::: "memory");

    for (int kc = 0; kc < 8; kc++) {
        asm volatile("cp.async.wait_group 1;" ::: "memory");
        __syncthreads();
        if (kc + 2 < 8) znx_load(sm, (kc + 2) % ZNST, kc + 2, tid, b, c);
        asm volatile("cp.async.commit_group;" ::: "memory");

        uint32_t sA = sbase + (kc % ZNST) * ZSTAGE;
        uint32_t sB = sA + ZA_TILE;
        #pragma unroll
        for (int kk = 0; kk < 2; kk++) {
            int kb = kk << 4;
            uint32_t ah[5][4], bh[2][4];
            uint32_t aofs = a_row * ZROWB + (kb + a_kof) * 2;
            #pragma unroll
            for (int mt = 0; mt < 5; mt++)
                ldsm4(ah[mt], sA + aofs + mt * 16 * ZROWB);
            uint32_t bofs = b_row * ZROWB + (kb + b_kof) * 2;
            #pragma unroll
            for (int np = 0; np < 2; np++)
                ldsm4(bh[np], sB + bofs + np * 16 * ZROWB);
            #pragma unroll
            for (int mt = 0; mt < 5; mt++)
                #pragma unroll
                for (int j = 0; j < 4; j++)
                    mma16816h(acc[mt][j], ah[mt], &bh[j >> 1][(j & 1) * 2]);
        }
        __syncthreads();
    }

    // epilogue: rows = n (x at n==64), cols = a; write single fp16 Zh
    #pragma unroll
    for (int mt = 0; mt < 5; mt++) {
        #pragma unroll
        for (int half = 0; half < 2; half++) {
            int r = mt * 16 + (lane >> 2) + half * 8;
            int zr;
            if (r < 64)       zr = 64 + b * NN + r;
            else if (r == 64) zr = b;
            else continue;
            #pragma unroll
            for (int j = 0; j < 4; j++) {
                int col = c * FF + wn + j * 8 + (lane & 3) * 2;
                *(__half2*)(g_Zh + (size_t)zr * KDIM + col) =
                    __halves2half2(__float2half_rn(acc[mt][j][half * 2]),
                                   __float2half_rn(acc[mt][j][half * 2 + 1]));
            }
        }
    }
}

// ====================== K7: big GEMM, single fp16 x single fp16 ======================
// out = Zh(4224x2048) @ Wh^T(2048x2048): 1 MMA per k16 subtile, 5-stage pipeline.
#define NST 5
#define ROWB 80
#define TILE_B (128 * ROWB)
#define STAGE_B (2 * TILE_B)          // Zh, Wh
#define GEMM_SMEM (NST * STAGE_B)     // 102400

__device__ __forceinline__ void g_load_stage(char* smembase, int st, int kc,
                                             int tid, int m0, int n0) {
    uint32_t so_base = smem_u32(smembase) + st * STAGE_B;
    #pragma unroll
    for (int t = 0; t < 2; t++) {
        int idx = tid + (t << 8);
        int row = idx >> 2, seg = idx & 3;
        size_t gA = (size_t)(m0 + row) * KDIM + (kc << 5) + (seg << 3);
        size_t gB = (size_t)(n0 + row) * KDIM + (kc << 5) + (seg << 3);
        uint32_t so = so_base + row * ROWB + (seg << 4);
        cp16(so,          g_Zh + gA);
        cp16(so + TILE_B, g_Wh + gB);
    }
}

__global__ __launch_bounds__(256, 1) void k_gemm_mma(float* __restrict__ out) {
    extern __shared__ char sm[];
    uint32_t sbase = smem_u32(sm);
    int tid = threadIdx.x;
    int lane = tid & 31, wid = tid >> 5;
    int m0 = blockIdx.y << 7, n0 = blockIdx.x << 7;
    int wm = (wid >> 2) << 6;
    int wn = (wid & 3) << 5;

    float c[4][4][4];
    #pragma unroll
    for (int i = 0; i < 4; i++)
        #pragma unroll
        for (int j = 0; j < 4; j++)
            #pragma unroll
            for (int q = 0; q < 4; q++) c[i][j][q] = 0.f;

    int a_row = wm + ((lane >> 3) & 1) * 8 + (lane & 7);
    int a_kof = (lane >> 4) * 8;
    int b_row = wn + ((lane >> 4) & 1) * 8 + (lane & 7);
    int b_kof = ((lane >> 3) & 1) * 8;

    #pragma unroll
    for (int st = 0; st < 4; st++) {
        g_load_stage(sm, st, st, tid, m0, n0);
        asm volatile("cp.async.commit_group;" ::: "memory");
    }

    for (int kc = 0; kc < 64; kc++) {
        asm volatile("cp.async.wait_group 3;" ::: "memory");
        __syncthreads();
        if (kc + 4 < 64) g_load_stage(sm, (kc + 4) % NST, kc + 4, tid, m0, n0);
        asm volatile("cp.async.commit_group;" ::: "memory");

        uint32_t sA = sbase + (kc % NST) * STAGE_B;
        uint32_t sB = sA + TILE_B;
        #pragma unroll
        for (int kk = 0; kk < 2; kk++) {
            int kb = kk << 4;
            uint32_t ah[4][4], bh[2][4];
            uint32_t aofs = a_row * ROWB + (kb + a_kof) * 2;
            #pragma unroll
            for (int mt = 0; mt < 4; mt++)
                ldsm4(ah[mt], sA + aofs + mt * 16 * ROWB);
            uint32_t bofs = b_row * ROWB + (kb + b_kof) * 2;
            #pragma unroll
            for (int np = 0; np < 2; np++)
                ldsm4(bh[np], sB + bofs + np * 16 * ROWB);
            #pragma unroll
            for (int mt = 0; mt < 4; mt++)
                #pragma unroll
                for (int j = 0; j < 4; j++)
                    mma16816h(c[mt][j], ah[mt], &bh[j >> 1][(j & 1) * 2]);
        }
        __syncthreads();
    }

    #pragma unroll
    for (int mt = 0; mt < 4; mt++) {
        int r0 = m0 + wm + mt * 16 + (lane >> 2);
        #pragma unroll
        for (int j = 0; j < 4; j++) {
            int col = n0 + wn + j * 8 + (lane & 3) * 2;
            if (r0 < MROWS)
                *(float2*)(out + (size_t)r0 * ODIM + col) =
                    make_float2(c[mt][j][0], c[mt][j][1]);
            if (r0 + 8 < MROWS)
                *(float2*)(out + (size_t)(r0 + 8) * ODIM + col) =
                    make_float2(c[mt][j][2], c[mt][j][3]);
        }
    }
}

extern "C" void kernel_launch(void* const* d_in, const int* in_sizes, int n_in,
                              void* d_out, int out_size) {
    const float* x  = (const float*)d_in[0];  // (64,8,256)
    const float* nb = (const float*)d_in[1];  // (64,64,8,256)
    const float* W1 = (const float*)d_in[2];  // (8,256)
    const float* W2 = (const float*)d_in[3];  // (8,256)
    const float* Wc = (const float*)d_in[4];  // (2048,8,256)
    float* out = (float*)d_out;

    static bool attr_set = false;
    if (!attr_set) {
        cudaFuncSetAttribute(k_gemm_mma, cudaFuncAttributeMaxDynamicSharedMemorySize,
                             GEMM_SMEM);
        cudaFuncSetAttribute(k_znx, cudaFuncAttributeMaxDynamicSharedMemorySize,
                             ZNX_SMEM);
        attr_set = true;
    }

    k_wsum<<<1, 256>>>(W1, W2);
    k_prep<<<NB_PREP, 256>>>(x, nb, Wc);
    k_t<<<256, 256>>>();
    k_adj<<<dim3(FF / 4, BB), 256>>>(x);
    k_znx<<<dim3(CC, BB), 256, ZNX_SMEM>>>();
    k_gemm_mma<<<dim3(16, 33), 256, GEMM_SMEM>>>(out);
}

// round 12
// speedup vs baseline: 7.8150x; 1.2432x over previous
#include <cuda_runtime.h>
#include <cuda_bf16.h>
#include <cuda_fp16.h>
#include <cstdint>

// Problem constants
#define BB 64
#define NN 64
#define CC 8
#define FF 256
#define KDIM 2048   // C*F
#define ODIM 2048   // OC*OF
#define MROWS 4160  // B + B*N rows of Z
#define MPAD 4224   // padded to 44*96 (= 33*128)

// Scratch (device globals; no dynamic allocation allowed)
__device__ float g_s1[BB];
__device__ float g_wraw[BB * NN];
__device__ float g_t[BB * KDIM];
// adj single fp16 (written directly by k_adj)
__device__ __half g_adjh[(size_t)BB * CC * FF * FF];  // 67 MB
// A-operand for znx GEMM: per b, 80 rows (64 neighbors, x, 15 pad), single fp16
__device__ __half g_nxh[(size_t)BB * 80 * KDIM];
// single fp16 Z and W for the big GEMM
__device__ __half g_Zh[(size_t)MPAD * KDIM];
__device__ __half g_Wh[(size_t)ODIM * KDIM];

__device__ __forceinline__ float blockReduce256(float v) {
    __shared__ float sh[8];
    #pragma unroll
    for (int o = 16; o > 0; o >>= 1) v += __shfl_down_sync(0xffffffffu, v, o);
    int lane = threadIdx.x & 31, wid = threadIdx.x >> 5;
    if (lane == 0) sh[wid] = v;
    __syncthreads();
    if (wid == 0) {
        v = (lane < 8) ? sh[lane] : 0.f;
        #pragma unroll
        for (int o = 4; o > 0; o >>= 1) v += __shfl_down_sync(0xffffffffu, v, o);
    }
    return v;
}

__device__ __forceinline__ float sqrt_approx(float v) {
    float r;
    asm("sqrt.approx.f32 %0, %1;" : "=f"(r) : "f"(v));
    return r;
}
__device__ __forceinline__ float rcp_approx(float v) {
    float r;
    asm("rcp.approx.f32 %0, %1;" : "=f"(r) : "f"(v));
    return r;
}

// K1 (merged): wsum (per-block, smem) + cvt_nx (blocks 0..5119)
//              + cvt_W (5120..7167) + Zh pad zero (7168..7231)
#define NB_NX   (80 * BB)             // 5120
#define NB_PREP (NB_NX + ODIM + (MPAD - MROWS))

__global__ void k_prep(const float* __restrict__ x, const float* __restrict__ nb,
                       const float* __restrict__ W1, const float* __restrict__ W2,
                       const float* __restrict__ Wc) {
    int bid = blockIdx.x;
    int tf = threadIdx.x;
    int c0 = tf * 8;
    if (bid < NB_NX) {
        // per-block W1/W2 column sums (replaces separate k_wsum launch)
        __shared__ float sws[2][FF];
        float wa = 0.f, wb = 0.f;
        #pragma unroll
        for (int k = 0; k < CC; k++) { wa += W1[k * FF + tf]; wb += W2[k * FF + tf]; }
        sws[0][tf] = wa; sws[1][tf] = wb;
        __syncthreads();
        // ---- cvt_nx: build 80-row A operand + fused s1/wraw reductions ----
        int r = bid % 80, b = bid / 80;
        size_t orow = ((size_t)b * 80 + r) * KDIM + c0;
        __align__(16) __half h[8];
        if (r <= 64) {
            const float* src = (r < 64) ? nb + ((size_t)b * NN + r) * KDIM
                                        : x + (size_t)b * KDIM;
            const float4* p = (const float4*)(src + c0);
            float4 v0 = p[0], v1 = p[1];
            float vv[8] = {v0.x, v0.y, v0.z, v0.w, v1.x, v1.y, v1.z, v1.w};
            #pragma unroll
            for (int i = 0; i < 8; i++) h[i] = __float2half_rn(vv[i]);
            *(uint4*)(g_nxh + orow) = *(uint4*)&h[0];
            const float* ws = sws[(r < 64) ? 1 : 0];
            float dot = 0.f;
            #pragma unroll
            for (int i = 0; i < 8; i++) dot += vv[i] * ws[(c0 + i) & (FF - 1)];
            dot = blockReduce256(dot);
            if (tf == 0) {
                if (r < 64) g_wraw[b * NN + r] = dot;
                else        g_s1[b] = dot;
            }
        } else {
            #pragma unroll
            for (int i = 0; i < 8; i++) h[i] = __float2half_rn(0.f);
            *(uint4*)(g_nxh + orow) = *(uint4*)&h[0];
        }
    } else if (bid < NB_NX + ODIM) {
        // ---- cvt_W: W -> single fp16 ----
        size_t row = bid - NB_NX;
        const float4* p = (const float4*)(Wc + row * KDIM + c0);
        float4 v0 = p[0], v1 = p[1];
        float vv[8] = {v0.x, v0.y, v0.z, v0.w, v1.x, v1.y, v1.z, v1.w};
        __align__(16) __half h[8];
        #pragma unroll
        for (int i = 0; i < 8; i++) h[i] = __float2half_rn(vv[i]);
        *(uint4*)(g_Wh + row * KDIM + c0) = *(uint4*)&h[0];
    } else {
        // ---- zero Zh pad rows ----
        size_t row = MROWS + (bid - NB_NX - ODIM);
        *(uint4*)(g_Zh + row * KDIM + c0) = make_uint4(0, 0, 0, 0);
    }
}

// K3: t[b,c,d] = sum_n nxh[b,n,c,d] * (s1[b]*wraw[b,n]); half2 vectorized
__global__ void k_t() {
    int b = blockIdx.x >> 2;
    int r0 = ((blockIdx.x & 3) << 9) | (threadIdx.x << 1);
    __shared__ float sw[NN];
    if (threadIdx.x < NN)
        sw[threadIdx.x] = g_wraw[b * NN + threadIdx.x] * g_s1[b];
    __syncthreads();
    const __half2* p = (const __half2*)(g_nxh + (size_t)b * 80 * KDIM + r0);
    float2 acc = make_float2(0.f, 0.f);
    #pragma unroll 8
    for (int n = 0; n < NN; n++) {
        float2 f = __half22float2(p[(size_t)n * (KDIM / 2)]);
        acc.x += f.x * sw[n];
        acc.y += f.y * sw[n];
    }
    *(float2*)(g_t + (size_t)b * KDIM + r0) = acc;
}

// K4: adj[b,c,a,d] = sgnroot(x_a t_d + x_d t_a) / (sum_c |sgnroot| + 1e-7)
// Issue-optimized: sqrt.approx + copysign + rcp.approx + half2 cvt.
__global__ void k_adj(const float* __restrict__ x) {
    int a0 = blockIdx.x << 2, b = blockIdx.y;
    __shared__ float sxa[CC][4], sta[CC][4];
    int t = threadIdx.x;
    if (t < 32)      sxa[t >> 2][t & 3] = x[b * KDIM + (t >> 2) * FF + a0 + (t & 3)];
    else if (t < 64) {
        int q = t - 32;
        sta[q >> 2][q & 3] = g_t[b * KDIM + (q >> 2) * FF + a0 + (q & 3)];
    }
    __syncthreads();
    int al = t >> 6;            // 0..3 -> which a in the group
    int d0 = (t & 63) << 2;     // 0..252, 4 d's per thread
    float gg[CC][4];
    float den[4] = {1e-7f, 1e-7f, 1e-7f, 1e-7f};
    #pragma unroll
    for (int c = 0; c < CC; c++) {
        float xa = sxa[c][al], ta = sta[c][al];
        float4 xd = *(const float4*)(x + b * KDIM + c * FF + d0);
        float4 td = *(const float4*)(g_t + b * KDIM + c * FF + d0);
        float fv[4] = {xa * td.x + xd.x * ta, xa * td.y + xd.y * ta,
                       xa * td.z + xd.z * ta, xa * td.w + xd.w * ta};
        #pragma unroll
        for (int i = 0; i < 4; i++) {
            float fa = fv[i];
            float sq = sqrt_approx(fmaxf(fabsf(fa), 1e-8f));
            den[i] += sq;                       // |g| == sq (non-negative)
            gg[c][i] = __int_as_float(
                (__float_as_int(sq) & 0x7fffffff) | (__float_as_int(fa) & 0x80000000));
        }
    }
    float inv[4];
    #pragma unroll
    for (int i = 0; i < 4; i++) inv[i] = rcp_approx(den[i]);
    int a = a0 + al;
    #pragma unroll
    for (int c = 0; c < CC; c++) {
        __half2 p0 = __float22half2_rn(make_float2(gg[c][0] * inv[0], gg[c][1] * inv[1]));
        __half2 p1 = __float22half2_rn(make_float2(gg[c][2] * inv[2], gg[c][3] * inv[3]));
        uint2 pk = make_uint2(*(uint32_t*)&p0, *(uint32_t*)&p1);
        *(uint2*)(g_adjh + (((size_t)(b * CC + c) * FF + a) * FF + d0)) = pk;
    }
}

// ---------- warp-MMA helpers (sm_80+ PTX only) ----------
__device__ __forceinline__ uint32_t smem_u32(const void* p) {
    uint32_t a;
    asm("{ .reg .u64 t; cvta.to.shared.u64 t, %1; cvt.u32.u64 %0, t; }"
        : "=r"(a) : "l"(p));
    return a;
}
__device__ __forceinline__ void cp16(uint32_t s, const void* g) {
    asm volatile("cp.async.cg.shared.global [%0], [%1], 16;" :: "r"(s), "l"(g) : "memory");
}
__device__ __forceinline__ void ldsm4(uint32_t* r, uint32_t addr) {
    asm volatile("ldmatrix.sync.aligned.m8n8.x4.shared.b16 {%0,%1,%2,%3}, [%4];"
                 : "=r"(r[0]), "=r"(r[1]), "=r"(r[2]), "=r"(r[3]) : "r"(addr));
}
__device__ __forceinline__ void mma16816h(float* c, const uint32_t* a, const uint32_t* b) {
    asm volatile(
        "mma.sync.aligned.m16n8k16.row.col.f32.f16.f16.f32 "
        "{%0,%1,%2,%3}, {%4,%5,%6,%7}, {%8,%9}, {%0,%1,%2,%3};"
        : "+f"(c[0]), "+f"(c[1]), "+f"(c[2]), "+f"(c[3])
        : "r"(a[0]), "r"(a[1]), "r"(a[2]), "r"(a[3]), "r"(b[0]), "r"(b[1]));
}

// ====================== K5: fused zn+zx tensor GEMM (proven) ======================
#define ZNST 3
#define ZROWB 80
#define ZA_TILE (80 * ZROWB)       // 6400
#define ZB_TILE (256 * ZROWB)      // 20480
#define ZSTAGE (ZA_TILE + ZB_TILE) // 26880
#define ZNX_SMEM (ZNST * ZSTAGE)   // 80640

__device__ __forceinline__ void znx_load(char* smbase, int st, int kc,
                                         int tid, int b, int c) {
    uint32_t so = smem_u32(smbase) + st * ZSTAGE;
    int kb = kc << 5;
    {
        int r = tid >> 2, s = tid & 3;
        size_t g = ((size_t)b * 80 + r) * KDIM + c * FF + kb + s * 8;
        cp16(so + r * ZROWB + (s << 4), g_nxh + g);
        if (tid < 64) {
            int idx2 = tid + 256;
            int r2 = idx2 >> 2, s2 = idx2 & 3;
            size_t g2 = ((size_t)b * 80 + r2) * KDIM + c * FF + kb + s2 * 8;
            cp16(so + r2 * ZROWB + (s2 << 4), g_nxh + g2);
        }
    }
    #pragma unroll
    for (int t = 0; t < 4; t++) {
        int idx = tid + (t << 8);
        int a = idx >> 2, s = idx & 3;
        size_t g = (((size_t)(b * CC + c)) * FF + a) * FF + kb + s * 8;
        cp16(so + ZA_TILE + a * ZROWB + (s << 4), g_adjh + g);
    }
}

__global__ __launch_bounds__(256, 1) void k_znx() {
    extern __shared__ char sm[];
    uint32_t sbase = smem_u32(sm);
    int tid = threadIdx.x;
    int lane = tid & 31, wid = tid >> 5;
    int c = blockIdx.x, b = blockIdx.y;
    int wn = wid << 5;

    float acc[5][4][4];
    #pragma unroll
    for (int i = 0; i < 5; i++)
        #pragma unroll
        for (int j = 0; j < 4; j++)
            #pragma unroll
            for (int q = 0; q < 4; q++) acc[i][j][q] = 0.f;

    int a_row = ((lane >> 3) & 1) * 8 + (lane & 7);
    int a_kof = (lane >> 4) * 8;
    int b_row = wn + ((lane >> 4) & 1) * 8 + (lane & 7);
    int b_kof = ((lane >> 3) & 1) * 8;

    znx_load(sm, 0, 0, tid, b, c);
    asm volatile("cp.async.commit_group;" ::: "memory");
    znx_load(sm, 1, 1, tid, b, c);
    asm volatile("cp.async.commit_group;" ::: "memory");

    for (int kc = 0; kc < 8; kc++) {
        asm volatile("cp.async.wait_group 1;" ::: "memory");
        __syncthreads();
        if (kc + 2 < 8) znx_load(sm, (kc + 2) % ZNST, kc + 2, tid, b, c);
        asm volatile("cp.async.commit_group;" ::: "memory");

        uint32_t sA = sbase + (kc % ZNST) * ZSTAGE;
        uint32_t sB = sA + ZA_TILE;
        #pragma unroll
        for (int kk = 0; kk < 2; kk++) {
            int kb = kk << 4;
            uint32_t ah[5][4], bh[2][4];
            uint32_t aofs = a_row * ZROWB + (kb + a_kof) * 2;
            #pragma unroll
            for (int mt = 0; mt < 5; mt++)
                ldsm4(ah[mt], sA + aofs + mt * 16 * ZROWB);
            uint32_t bofs = b_row * ZROWB + (kb + b_kof) * 2;
            #pragma unroll
            for (int np = 0; np < 2; np++)
                ldsm4(bh[np], sB + bofs + np * 16 * ZROWB);
            #pragma unroll
            for (int mt = 0; mt < 5; mt++)
                #pragma unroll
                for (int j = 0; j < 4; j++)
                    mma16816h(acc[mt][j], ah[mt], &bh[j >> 1][(j & 1) * 2]);
        }
        __syncthreads();
    }

    // epilogue: rows = n (x at n==64), cols = a; write single fp16 Zh
    #pragma unroll
    for (int mt = 0; mt < 5; mt++) {
        #pragma unroll
        for (int half = 0; half < 2; half++) {
            int r = mt * 16 + (lane >> 2) + half * 8;
            int zr;
            if (r < 64)       zr = 64 + b * NN + r;
            else if (r == 64) zr = b;
            else continue;
            #pragma unroll
            for (int j = 0; j < 4; j++) {
                int col = c * FF + wn + j * 8 + (lane & 3) * 2;
                *(__half2*)(g_Zh + (size_t)zr * KDIM + col) =
                    __halves2half2(__float2half_rn(acc[mt][j][half * 2]),
                                   __float2half_rn(acc[mt][j][half * 2 + 1]));
            }
        }
    }
}

// ====================== K7: big GEMM, 96x128 tiles, occ 2 ======================
// out = Zh(4224x2048) @ Wh^T(2048x2048). 704 CTAs, 2 CTAs/SM -> smaller tail.
#define NST 5
#define ROWB 80
#define GM 96
#define A_TILE_B (GM * ROWB)          // 7680
#define B_TILE_B (128 * ROWB)         // 10240
#define STAGE_B (A_TILE_B + B_TILE_B) // 17920
#define GEMM_SMEM (NST * STAGE_B)     // 89600

__device__ __forceinline__ void g_load_stage(char* smembase, int st, int kc,
                                             int tid, int m0, int n0) {
    uint32_t so_base = smem_u32(smembase) + st * STAGE_B;
    // A: 96 rows x 4 segs = 384 loads
    {
        int row = tid >> 2, seg = tid & 3;
        size_t gA = (size_t)(m0 + row) * KDIM + (kc << 5) + (seg << 3);
        cp16(so_base + row * ROWB + (seg << 4), g_Zh + gA);
        if (tid < 128) {
            int idx = tid + 256;
            int row2 = idx >> 2, seg2 = idx & 3;
            size_t gA2 = (size_t)(m0 + row2) * KDIM + (kc << 5) + (seg2 << 3);
            cp16(so_base + row2 * ROWB + (seg2 << 4), g_Zh + gA2);
        }
    }
    // B: 128 rows x 4 segs = 512 loads
    #pragma unroll
    for (int t = 0; t < 2; t++) {
        int idx = tid + (t << 8);
        int row = idx >> 2, seg = idx & 3;
        size_t gB = (size_t)(n0 + row) * KDIM + (kc << 5) + (seg << 3);
        cp16(so_base + A_TILE_B + row * ROWB + (seg << 4), g_Wh + gB);
    }
}

__global__ __launch_bounds__(256, 2) void k_gemm_mma(float* __restrict__ out) {
    extern __shared__ char sm[];
    uint32_t sbase = smem_u32(sm);
    int tid = threadIdx.x;
    int lane = tid & 31, wid = tid >> 5;
    int m0 = blockIdx.y * GM, n0 = blockIdx.x << 7;
    int wm = (wid >> 2) * 48;       // 0 / 48 (3 m16 frags each)
    int wn = (wid & 3) << 5;

    float c[3][4][4];
    #pragma unroll
    for (int i = 0; i < 3; i++)
        #pragma unroll
        for (int j = 0; j < 4; j++)
            #pragma unroll
            for (int q = 0; q < 4; q++) c[i][j][q] = 0.f;

    int a_row = wm + ((lane >> 3) & 1) * 8 + (lane & 7);
    int a_kof = (lane >> 4) * 8;
    int b_row = wn + ((lane >> 4) & 1) * 8 + (lane & 7);
    int b_kof = ((lane >> 3) & 1) * 8;

    #pragma unroll
    for (int st = 0; st < 4; st++) {
        g_load_stage(sm, st, st, tid, m0, n0);
        asm volatile("cp.async.commit_group;" ::: "memory");
    }

    for (int kc = 0; kc < 64; kc++) {
        asm volatile("cp.async.wait_group 3;" ::: "memory");
        __syncthreads();
        if (kc + 4 < 64) g_load_stage(sm, (kc + 4) % NST, kc + 4, tid, m0, n0);
        asm volatile("cp.async.commit_group;" ::: "memory");

        uint32_t sA = sbase + (kc % NST) * STAGE_B;
        uint32_t sB = sA + A_TILE_B;
        #pragma unroll
        for (int kk = 0; kk < 2; kk++) {
            int kb = kk << 4;
            uint32_t ah[3][4], bh[2][4];
            uint32_t aofs = a_row * ROWB + (kb + a_kof) * 2;
            #pragma unroll
            for (int mt = 0; mt < 3; mt++)
                ldsm4(ah[mt], sA + aofs + mt * 16 * ROWB);
            uint32_t bofs = b_row * ROWB + (kb + b_kof) * 2;
            #pragma unroll
            for (int np = 0; np < 2; np++)
                ldsm4(bh[np], sB + bofs + np * 16 * ROWB);
            #pragma unroll
            for (int mt = 0; mt < 3; mt++)
                #pragma unroll
                for (int j = 0; j < 4; j++)
                    mma16816h(c[mt][j], ah[mt], &bh[j >> 1][(j & 1) * 2]);
        }
        __syncthreads();
    }

    #pragma unroll
    for (int mt = 0; mt < 3; mt++) {
        int r0 = m0 + wm + mt * 16 + (lane >> 2);
        #pragma unroll
        for (int j = 0; j < 4; j++) {
            int col = n0 + wn + j * 8 + (lane & 3) * 2;
            if (r0 < MROWS)
                *(float2*)(out + (size_t)r0 * ODIM + col) =
                    make_float2(c[mt][j][0], c[mt][j][1]);
            if (r0 + 8 < MROWS)
                *(float2*)(out + (size_t)(r0 + 8) * ODIM + col) =
                    make_float2(c[mt][j][2], c[mt][j][3]);
        }
    }
}

extern "C" void kernel_launch(void* const* d_in, const int* in_sizes, int n_in,
                              void* d_out, int out_size) {
    const float* x  = (const float*)d_in[0];  // (64,8,256)
    const float* nb = (const float*)d_in[1];  // (64,64,8,256)
    const float* W1 = (const float*)d_in[2];  // (8,256)
    const float* W2 = (const float*)d_in[3];  // (8,256)
    const float* Wc = (const float*)d_in[4];  // (2048,8,256)
    float* out = (float*)d_out;

    static bool attr_set = false;
    if (!attr_set) {
        cudaFuncSetAttribute(k_gemm_mma, cudaFuncAttributeMaxDynamicSharedMemorySize,
                             GEMM_SMEM);
        cudaFuncSetAttribute(k_znx, cudaFuncAttributeMaxDynamicSharedMemorySize,
                             ZNX_SMEM);
        attr_set = true;
    }

    k_prep<<<NB_PREP, 256>>>(x, nb, W1, W2, Wc);
    k_t<<<256, 256>>>();
    k_adj<<<dim3(FF / 4, BB), 256>>>(x);
    k_znx<<<dim3(CC, BB), 256, ZNX_SMEM>>>();
    k_gemm_mma<<<dim3(16, MPAD / GM), 256, GEMM_SMEM>>>(out);
}